// round 1
// baseline (speedup 1.0000x reference)
#include <cuda_runtime.h>

// Fixed problem shapes
#define NB 4
#define NT 2048
#define NC 1024
#define NH 16
#define DH 64
#define NM (NB*NT)   // 8192 rows

// Scratch (allocation-free rule: __device__ globals)
__device__ float g_q[(size_t)NB*NH*NT*DH];
__device__ float g_k[(size_t)NB*NH*NT*DH];
__device__ float g_v[(size_t)NB*NH*NT*DH];
__device__ float g_attn[(size_t)NB*NT*NC];

// ---------------------------------------------------------------------------
// GEMM: C[M,N] = A[M,K] * B[N,K]^T   (both A and B are K-major row-major)
// 128x128 block tile, BK=8, 256 threads, 8x8 micro-tile per thread.
// ---------------------------------------------------------------------------

// QKV projection: grid.z selects Wq/Wk/Wv; output scattered to [B,H,T,HS].
__global__ __launch_bounds__(256) void qkv_kernel(
    const float* __restrict__ x,
    const float* __restrict__ Wq,
    const float* __restrict__ Wk,
    const float* __restrict__ Wv)
{
    __shared__ float sA[8][128];
    __shared__ float sB[8][128];

    const float* W;
    float* out;
    if (blockIdx.z == 0)      { W = Wq; out = g_q; }
    else if (blockIdx.z == 1) { W = Wk; out = g_k; }
    else                      { W = Wv; out = g_v; }

    const int tid  = threadIdx.x;
    const int row0 = blockIdx.y * 128;
    const int col0 = blockIdx.x * 128;
    const int lr = tid >> 1;          // 0..127 load row
    const int lc = (tid & 1) * 4;     // 0 or 4
    const int ty = tid >> 4;          // 0..15
    const int tx = tid & 15;          // 0..15

    const float* Ag = x + (size_t)(row0 + lr) * NC + lc;
    const float* Bg = W + (size_t)(col0 + lr) * NC + lc;

    float acc[8][8] = {};

    for (int k0 = 0; k0 < NC; k0 += 8) {
        float4 av = *(const float4*)(Ag + k0);
        float4 bv = *(const float4*)(Bg + k0);
        sA[lc+0][lr] = av.x; sA[lc+1][lr] = av.y;
        sA[lc+2][lr] = av.z; sA[lc+3][lr] = av.w;
        sB[lc+0][lr] = bv.x; sB[lc+1][lr] = bv.y;
        sB[lc+2][lr] = bv.z; sB[lc+3][lr] = bv.w;
        __syncthreads();
        #pragma unroll
        for (int kk = 0; kk < 8; kk++) {
            float a[8], b[8];
            *(float4*)&a[0] = *(const float4*)&sA[kk][ty*8];
            *(float4*)&a[4] = *(const float4*)&sA[kk][ty*8+4];
            *(float4*)&b[0] = *(const float4*)&sB[kk][tx*8];
            *(float4*)&b[4] = *(const float4*)&sB[kk][tx*8+4];
            #pragma unroll
            for (int i = 0; i < 8; i++)
                #pragma unroll
                for (int j = 0; j < 8; j++)
                    acc[i][j] += a[i] * b[j];
        }
        __syncthreads();
    }

    // Scatter epilogue: row m -> (b,t); col n -> (h,d). 8-wide chunks never
    // cross a head boundary (HS=64, chunks 8-aligned).
    const int n0 = col0 + tx*8;
    const int h  = n0 / DH;
    const int d0 = n0 % DH;
    #pragma unroll
    for (int i = 0; i < 8; i++) {
        int m = row0 + ty*8 + i;
        int b = m / NT, t = m % NT;
        float* o = out + (((size_t)b*NH + h)*NT + t)*DH + d0;
        *(float4*)(o)     = make_float4(acc[i][0], acc[i][1], acc[i][2], acc[i][3]);
        *(float4*)(o + 4) = make_float4(acc[i][4], acc[i][5], acc[i][6], acc[i][7]);
    }
}

// Output projection: Y = attn * Wo^T + bo, natural [M,N] output.
__global__ __launch_bounds__(256) void oproj_kernel(
    const float* __restrict__ Wo,
    const float* __restrict__ bo,
    float* __restrict__ out)
{
    __shared__ float sA[8][128];
    __shared__ float sB[8][128];

    const int tid  = threadIdx.x;
    const int row0 = blockIdx.y * 128;
    const int col0 = blockIdx.x * 128;
    const int lr = tid >> 1;
    const int lc = (tid & 1) * 4;
    const int ty = tid >> 4;
    const int tx = tid & 15;

    const float* Ag = g_attn + (size_t)(row0 + lr) * NC + lc;
    const float* Bg = Wo     + (size_t)(col0 + lr) * NC + lc;

    float acc[8][8] = {};

    for (int k0 = 0; k0 < NC; k0 += 8) {
        float4 av = *(const float4*)(Ag + k0);
        float4 bv = *(const float4*)(Bg + k0);
        sA[lc+0][lr] = av.x; sA[lc+1][lr] = av.y;
        sA[lc+2][lr] = av.z; sA[lc+3][lr] = av.w;
        sB[lc+0][lr] = bv.x; sB[lc+1][lr] = bv.y;
        sB[lc+2][lr] = bv.z; sB[lc+3][lr] = bv.w;
        __syncthreads();
        #pragma unroll
        for (int kk = 0; kk < 8; kk++) {
            float a[8], b[8];
            *(float4*)&a[0] = *(const float4*)&sA[kk][ty*8];
            *(float4*)&a[4] = *(const float4*)&sA[kk][ty*8+4];
            *(float4*)&b[0] = *(const float4*)&sB[kk][tx*8];
            *(float4*)&b[4] = *(const float4*)&sB[kk][tx*8+4];
            #pragma unroll
            for (int i = 0; i < 8; i++)
                #pragma unroll
                for (int j = 0; j < 8; j++)
                    acc[i][j] += a[i] * b[j];
        }
        __syncthreads();
    }

    const int n0 = col0 + tx*8;
    float bias[8];
    *(float4*)&bias[0] = *(const float4*)(bo + n0);
    *(float4*)&bias[4] = *(const float4*)(bo + n0 + 4);
    #pragma unroll
    for (int i = 0; i < 8; i++) {
        int m = row0 + ty*8 + i;
        float* o = out + (size_t)m*NC + n0;
        *(float4*)(o)     = make_float4(acc[i][0]+bias[0], acc[i][1]+bias[1],
                                        acc[i][2]+bias[2], acc[i][3]+bias[3]);
        *(float4*)(o + 4) = make_float4(acc[i][4]+bias[4], acc[i][5]+bias[5],
                                        acc[i][6]+bias[6], acc[i][7]+bias[7]);
    }
}

// ---------------------------------------------------------------------------
// Causal flash attention. One block = 64 query rows of one (b,h).
// Br=Bc=64, HS=64. 128 threads; thread (ty,tx) owns 4 query rows x 8 cols.
// smem: sQt[d][i] (stride 68), sKP (K as [d][j], reused as P [j][i], stride 68),
//       sV[j][d] (stride 64). Total 52224 B dynamic.
// ---------------------------------------------------------------------------
#define ATTN_SMEM ((64*68*2 + 64*64) * 4)

__global__ __launch_bounds__(128) void attn_kernel()
{
    extern __shared__ float sm[];
    float* sQt = sm;                // [64][68]  (d-major, i cols)
    float* sKP = sm + 64*68;        // K: [d][j]; later P: [j][i]
    float* sV  = sm + 2*64*68;      // [j][d], stride 64

    const int tid = threadIdx.x;
    const int qb  = gridDim.x - 1 - blockIdx.x;   // heavy blocks first
    const int bh  = blockIdx.y;
    const int ty  = tid >> 3;       // 0..15
    const int tx  = tid & 7;        // 0..7
    const int r0  = ty * 4;         // query rows (within tile)
    const int c0  = tx * 8;         // key cols / head-dim cols

    // load-lane mapping (coalesced, conflict-light)
    const int d4 = (tid & 15) * 4;  // 0..60
    const int j0 = tid >> 4;        // 0..7

    const float* Qg = g_q + ((size_t)bh*NT + (size_t)qb*64) * DH;

    // Load Q tile transposed, fold the *sqrt(HS)=8 scale in.
    for (int i = j0; i < 64; i += 8) {
        float4 qv = *(const float4*)(Qg + i*DH + d4);
        sQt[(d4+0)*68 + i] = qv.x * 8.0f;
        sQt[(d4+1)*68 + i] = qv.y * 8.0f;
        sQt[(d4+2)*68 + i] = qv.z * 8.0f;
        sQt[(d4+3)*68 + i] = qv.w * 8.0f;
    }

    float m_i[4], l_i[4], acc[4][8];
    #pragma unroll
    for (int r = 0; r < 4; r++) {
        m_i[r] = -1e30f; l_i[r] = 0.0f;
        #pragma unroll
        for (int c = 0; c < 8; c++) acc[r][c] = 0.0f;
    }

    for (int kt = 0; kt <= qb; kt++) {
        __syncthreads();  // Q ready (iter 0) / prev GEMM2 done with sKP,sV

        const float* Kg = g_k + ((size_t)bh*NT + (size_t)kt*64) * DH;
        const float* Vg = g_v + ((size_t)bh*NT + (size_t)kt*64) * DH;
        for (int j = j0; j < 64; j += 8) {
            float4 kv = *(const float4*)(Kg + j*DH + d4);
            sKP[(d4+0)*68 + j] = kv.x;
            sKP[(d4+1)*68 + j] = kv.y;
            sKP[(d4+2)*68 + j] = kv.z;
            sKP[(d4+3)*68 + j] = kv.w;
            float4 vv = *(const float4*)(Vg + j*DH + d4);
            *(float4*)&sV[j*64 + d4] = vv;
        }
        __syncthreads();

        // S = Q K^T  (scaled)
        float s[4][8] = {};
        #pragma unroll 8
        for (int d = 0; d < 64; d++) {
            float4 q4  = *(const float4*)(sQt + d*68 + r0);
            float4 k4a = *(const float4*)(sKP + d*68 + c0);
            float4 k4b = *(const float4*)(sKP + d*68 + c0 + 4);
            float qv[4] = {q4.x, q4.y, q4.z, q4.w};
            float kv[8] = {k4a.x, k4a.y, k4a.z, k4a.w,
                           k4b.x, k4b.y, k4b.z, k4b.w};
            #pragma unroll
            for (int r = 0; r < 4; r++)
                #pragma unroll
                for (int c = 0; c < 8; c++)
                    s[r][c] += qv[r] * kv[c];
        }

        // Causal mask (only the diagonal tile is partial)
        if (kt == qb) {
            #pragma unroll
            for (int r = 0; r < 4; r++)
                #pragma unroll
                for (int c = 0; c < 8; c++)
                    if (c0 + c > r0 + r) s[r][c] = -1e30f;
        }

        // Online softmax update (8 lanes share each row group)
        #pragma unroll
        for (int r = 0; r < 4; r++) {
            float mx = s[r][0];
            #pragma unroll
            for (int c = 1; c < 8; c++) mx = fmaxf(mx, s[r][c]);
            mx = fmaxf(mx, __shfl_xor_sync(0xffffffffu, mx, 1));
            mx = fmaxf(mx, __shfl_xor_sync(0xffffffffu, mx, 2));
            mx = fmaxf(mx, __shfl_xor_sync(0xffffffffu, mx, 4));
            float mnew = fmaxf(m_i[r], mx);
            float al   = __expf(m_i[r] - mnew);
            float rs = 0.0f;
            #pragma unroll
            for (int c = 0; c < 8; c++) {
                float p = __expf(s[r][c] - mnew);
                s[r][c] = p;
                rs += p;
            }
            rs += __shfl_xor_sync(0xffffffffu, rs, 1);
            rs += __shfl_xor_sync(0xffffffffu, rs, 2);
            rs += __shfl_xor_sync(0xffffffffu, rs, 4);
            l_i[r] = l_i[r] * al + rs;
            m_i[r] = mnew;
            #pragma unroll
            for (int c = 0; c < 8; c++) acc[r][c] *= al;
        }

        __syncthreads();  // everyone done reading sKP as K

        // Write P transposed: sKP[j][i]
        #pragma unroll
        for (int c = 0; c < 8; c++)
            #pragma unroll
            for (int r = 0; r < 4; r++)
                sKP[(c0 + c)*68 + r0 + r] = s[r][c];
        __syncthreads();

        // O += P V
        #pragma unroll 8
        for (int j = 0; j < 64; j++) {
            float4 p4  = *(const float4*)(sKP + j*68 + r0);
            float4 v4a = *(const float4*)(sV  + j*64 + c0);
            float4 v4b = *(const float4*)(sV  + j*64 + c0 + 4);
            float pv[4] = {p4.x, p4.y, p4.z, p4.w};
            float vv[8] = {v4a.x, v4a.y, v4a.z, v4a.w,
                           v4b.x, v4b.y, v4b.z, v4b.w};
            #pragma unroll
            for (int r = 0; r < 4; r++)
                #pragma unroll
                for (int c = 0; c < 8; c++)
                    acc[r][c] += pv[r] * vv[c];
        }
    }

    // Epilogue: normalize, write [B,T,H*HS] (concat-heads layout)
    const int b = bh / NH, h = bh % NH;
    #pragma unroll
    for (int r = 0; r < 4; r++) {
        float inv = 1.0f / l_i[r];
        int t = qb*64 + r0 + r;
        float* o = g_attn + ((size_t)b*NT + t)*NC + h*DH + c0;
        *(float4*)(o)     = make_float4(acc[r][0]*inv, acc[r][1]*inv,
                                        acc[r][2]*inv, acc[r][3]*inv);
        *(float4*)(o + 4) = make_float4(acc[r][4]*inv, acc[r][5]*inv,
                                        acc[r][6]*inv, acc[r][7]*inv);
    }
}

// ---------------------------------------------------------------------------

extern "C" void kernel_launch(void* const* d_in, const int* in_sizes, int n_in,
                              void* d_out, int out_size)
{
    const float* x  = (const float*)d_in[0];
    const float* Wq = (const float*)d_in[1];
    const float* Wk = (const float*)d_in[2];
    const float* Wv = (const float*)d_in[3];
    const float* Wo = (const float*)d_in[4];
    const float* bo = (const float*)d_in[5];
    float* out = (float*)d_out;

    // Host-side attribute set (not a stream op; capture-safe, idempotent).
    cudaFuncSetAttribute(attn_kernel,
                         cudaFuncAttributeMaxDynamicSharedMemorySize, ATTN_SMEM);

    qkv_kernel <<< dim3(NC/128, NM/128, 3), 256 >>> (x, Wq, Wk, Wv);
    attn_kernel<<< dim3(NT/64, NB*NH), 128, ATTN_SMEM >>> ();
    oproj_kernel<<< dim3(NC/128, NM/128), 256 >>> (Wo, bo, out);
}

// round 4
// speedup vs baseline: 1.1159x; 1.1159x over previous
#include <cuda_runtime.h>
#include <cstdint>

// Fixed problem shapes
#define NB 4
#define NT 2048
#define NC 1024
#define NH 16
#define DH 64
#define NM (NB*NT)   // 8192 rows

// Scratch (allocation-free rule: __device__ globals)
__device__ float g_q[(size_t)NB*NH*NT*DH];
__device__ float g_k[(size_t)NB*NH*NT*DH];
__device__ float g_v[(size_t)NB*NH*NT*DH];
__device__ float g_attn[(size_t)NB*NT*NC];

__device__ __forceinline__ float tf32_rna(float a) {
    uint32_t u;
    asm("cvt.rna.tf32.f32 %0, %1;" : "=r"(u) : "f"(a));
    return __uint_as_float(u);
}

#define MMA_TF32(d, a, b) \
    asm volatile("mma.sync.aligned.m16n8k8.row.col.f32.tf32.tf32.f32 " \
        "{%0,%1,%2,%3}, {%4,%5,%6,%7}, {%8,%9}, {%0,%1,%2,%3};" \
        : "+f"(d[0]), "+f"(d[1]), "+f"(d[2]), "+f"(d[3]) \
        : "r"(a[0]), "r"(a[1]), "r"(a[2]), "r"(a[3]), "r"(b[0]), "r"(b[1]))

// ===========================================================================
// 3xTF32 tensor GEMM via mma.sync:  C[M,N] = A[M,K] * B[N,K]^T  (K-major both)
// Block 128x128x16, 256 thr, 8 warps (2x4), warp tile 64x32.
// mode 0: QKV projection (z selects W; scatter out to [B,H,T,DH])
// mode 1: output projection (+bias, natural [M,N])
// ===========================================================================
#define BM 128
#define BN 128
#define BK 16
#define LDS 20   // padded float stride

__global__ __launch_bounds__(256) void mma_gemm_kernel(
    const float* __restrict__ x,
    const float* __restrict__ Wq,
    const float* __restrict__ Wk,
    const float* __restrict__ Wv,
    const float* __restrict__ bias,
    float* __restrict__ Cout,
    int mode)
{
    __shared__ float sAhi[BM*LDS], sAlo[BM*LDS];
    __shared__ float sBhi[BN*LDS], sBlo[BN*LDS];

    const int tid  = threadIdx.x;
    const int wid  = tid >> 5;
    const int lane = tid & 31;
    const int warp_m = wid >> 2;      // 0..1 -> 64-row slice
    const int warp_n = wid & 3;       // 0..3 -> 32-col slice
    const int qr = lane >> 2;         // 0..7
    const int qc = lane & 3;          // 0..3

    const int row0 = blockIdx.y * BM;
    const int col0 = blockIdx.x * BN;

    const float* A;
    const float* W;
    float* outq = 0;
    if (mode == 0) {
        A = x;
        if (blockIdx.z == 0)      { W = Wq; outq = g_q; }
        else if (blockIdx.z == 1) { W = Wk; outq = g_k; }
        else                      { W = Wv; outq = g_v; }
    } else {
        A = g_attn;
        W = Wq;   // Wo passed in slot 0
    }

    // global loader: 2 threads per row, 8 floats each
    const int lr = tid >> 1;
    const int lc = (tid & 1) * 8;
    const float* Ap = A + (size_t)(row0 + lr) * NC + lc;
    const float* Bp = W + (size_t)(col0 + lr) * NC + lc;

    float acc[4][4][4] = {};

    float4 pa0 = *(const float4*)(Ap);
    float4 pa1 = *(const float4*)(Ap + 4);
    float4 pb0 = *(const float4*)(Bp);
    float4 pb1 = *(const float4*)(Bp + 4);
    Ap += BK; Bp += BK;

    for (int c = 0; c < NC/BK; c++) {
        // hi/lo split + store
        const int so = lr*LDS + lc;
        {
            float4 h, l;
            h = make_float4(tf32_rna(pa0.x), tf32_rna(pa0.y), tf32_rna(pa0.z), tf32_rna(pa0.w));
            l = make_float4(tf32_rna(pa0.x - h.x), tf32_rna(pa0.y - h.y),
                            tf32_rna(pa0.z - h.z), tf32_rna(pa0.w - h.w));
            *(float4*)&sAhi[so] = h; *(float4*)&sAlo[so] = l;
            h = make_float4(tf32_rna(pa1.x), tf32_rna(pa1.y), tf32_rna(pa1.z), tf32_rna(pa1.w));
            l = make_float4(tf32_rna(pa1.x - h.x), tf32_rna(pa1.y - h.y),
                            tf32_rna(pa1.z - h.z), tf32_rna(pa1.w - h.w));
            *(float4*)&sAhi[so+4] = h; *(float4*)&sAlo[so+4] = l;
            h = make_float4(tf32_rna(pb0.x), tf32_rna(pb0.y), tf32_rna(pb0.z), tf32_rna(pb0.w));
            l = make_float4(tf32_rna(pb0.x - h.x), tf32_rna(pb0.y - h.y),
                            tf32_rna(pb0.z - h.z), tf32_rna(pb0.w - h.w));
            *(float4*)&sBhi[so] = h; *(float4*)&sBlo[so] = l;
            h = make_float4(tf32_rna(pb1.x), tf32_rna(pb1.y), tf32_rna(pb1.z), tf32_rna(pb1.w));
            l = make_float4(tf32_rna(pb1.x - h.x), tf32_rna(pb1.y - h.y),
                            tf32_rna(pb1.z - h.z), tf32_rna(pb1.w - h.w));
            *(float4*)&sBhi[so+4] = h; *(float4*)&sBlo[so+4] = l;
        }
        __syncthreads();

        if (c + 1 < NC/BK) {   // prefetch next chunk (overlaps with MMAs)
            pa0 = *(const float4*)(Ap);
            pa1 = *(const float4*)(Ap + 4);
            pb0 = *(const float4*)(Bp);
            pb1 = *(const float4*)(Bp + 4);
            Ap += BK; Bp += BK;
        }

        #pragma unroll
        for (int kk = 0; kk < 2; kk++) {
            const int kb = kk*8 + qc;
            uint32_t Ah[4][4], Al[4][4], Bh[4][2], Bl[4][2];
            #pragma unroll
            for (int mi = 0; mi < 4; mi++) {
                const int ar = warp_m*64 + mi*16 + qr;
                Ah[mi][0] = __float_as_uint(sAhi[ar*LDS + kb]);
                Ah[mi][1] = __float_as_uint(sAhi[(ar+8)*LDS + kb]);
                Ah[mi][2] = __float_as_uint(sAhi[ar*LDS + kb + 4]);
                Ah[mi][3] = __float_as_uint(sAhi[(ar+8)*LDS + kb + 4]);
                Al[mi][0] = __float_as_uint(sAlo[ar*LDS + kb]);
                Al[mi][1] = __float_as_uint(sAlo[(ar+8)*LDS + kb]);
                Al[mi][2] = __float_as_uint(sAlo[ar*LDS + kb + 4]);
                Al[mi][3] = __float_as_uint(sAlo[(ar+8)*LDS + kb + 4]);
            }
            #pragma unroll
            for (int ni = 0; ni < 4; ni++) {
                const int br = warp_n*32 + ni*8 + qr;
                Bh[ni][0] = __float_as_uint(sBhi[br*LDS + kb]);
                Bh[ni][1] = __float_as_uint(sBhi[br*LDS + kb + 4]);
                Bl[ni][0] = __float_as_uint(sBlo[br*LDS + kb]);
                Bl[ni][1] = __float_as_uint(sBlo[br*LDS + kb + 4]);
            }
            #pragma unroll
            for (int mi = 0; mi < 4; mi++)
                #pragma unroll
                for (int ni = 0; ni < 4; ni++) {
                    MMA_TF32(acc[mi][ni], Ah[mi], Bh[ni]);
                    MMA_TF32(acc[mi][ni], Al[mi], Bh[ni]);
                    MMA_TF32(acc[mi][ni], Ah[mi], Bl[ni]);
                }
        }
        __syncthreads();
    }

    // Epilogue: c0,c1 at (row, n..n+1); c2,c3 at (row+8, n..n+1)
    #pragma unroll
    for (int mi = 0; mi < 4; mi++) {
        const int m0 = row0 + warp_m*64 + mi*16 + qr;
        #pragma unroll
        for (int ni = 0; ni < 4; ni++) {
            const int n = col0 + warp_n*32 + ni*8 + qc*2;
            if (mode == 0) {
                const int h = n >> 6, d = n & 63;
                #pragma unroll
                for (int half = 0; half < 2; half++) {
                    const int m = m0 + half*8;
                    const int b = m >> 11, t = m & (NT-1);
                    float* o = outq + (((size_t)b*NH + h)*NT + t)*DH + d;
                    *(float2*)o = make_float2(acc[mi][ni][half*2], acc[mi][ni][half*2+1]);
                }
            } else {
                const float2 bv = *(const float2*)(bias + n);
                #pragma unroll
                for (int half = 0; half < 2; half++) {
                    const int m = m0 + half*8;
                    float* o = Cout + (size_t)m*NC + n;
                    *(float2*)o = make_float2(acc[mi][ni][half*2] + bv.x,
                                              acc[mi][ni][half*2+1] + bv.y);
                }
            }
        }
    }
}

// ---------------------------------------------------------------------------
// Causal flash attention (fp32 SIMT, unchanged from R1).
// ---------------------------------------------------------------------------
#define ATTN_SMEM ((64*68*2 + 64*64) * 4)

__global__ __launch_bounds__(128) void attn_kernel()
{
    extern __shared__ float sm[];
    float* sQt = sm;
    float* sKP = sm + 64*68;
    float* sV  = sm + 2*64*68;

    const int tid = threadIdx.x;
    const int qb  = gridDim.x - 1 - blockIdx.x;
    const int bh  = blockIdx.y;
    const int ty  = tid >> 3;
    const int tx  = tid & 7;
    const int r0  = ty * 4;
    const int c0  = tx * 8;

    const int d4 = (tid & 15) * 4;
    const int j0 = tid >> 4;

    const float* Qg = g_q + ((size_t)bh*NT + (size_t)qb*64) * DH;

    for (int i = j0; i < 64; i += 8) {
        float4 qv = *(const float4*)(Qg + i*DH + d4);
        sQt[(d4+0)*68 + i] = qv.x * 8.0f;
        sQt[(d4+1)*68 + i] = qv.y * 8.0f;
        sQt[(d4+2)*68 + i] = qv.z * 8.0f;
        sQt[(d4+3)*68 + i] = qv.w * 8.0f;
    }

    float m_i[4], l_i[4], acc[4][8];
    #pragma unroll
    for (int r = 0; r < 4; r++) {
        m_i[r] = -1e30f; l_i[r] = 0.0f;
        #pragma unroll
        for (int c = 0; c < 8; c++) acc[r][c] = 0.0f;
    }

    for (int kt = 0; kt <= qb; kt++) {
        __syncthreads();

        const float* Kg = g_k + ((size_t)bh*NT + (size_t)kt*64) * DH;
        const float* Vg = g_v + ((size_t)bh*NT + (size_t)kt*64) * DH;
        for (int j = j0; j < 64; j += 8) {
            float4 kv = *(const float4*)(Kg + j*DH + d4);
            sKP[(d4+0)*68 + j] = kv.x;
            sKP[(d4+1)*68 + j] = kv.y;
            sKP[(d4+2)*68 + j] = kv.z;
            sKP[(d4+3)*68 + j] = kv.w;
            float4 vv = *(const float4*)(Vg + j*DH + d4);
            *(float4*)&sV[j*64 + d4] = vv;
        }
        __syncthreads();

        float s[4][8] = {};
        #pragma unroll 8
        for (int d = 0; d < 64; d++) {
            float4 q4  = *(const float4*)(sQt + d*68 + r0);
            float4 k4a = *(const float4*)(sKP + d*68 + c0);
            float4 k4b = *(const float4*)(sKP + d*68 + c0 + 4);
            float qv[4] = {q4.x, q4.y, q4.z, q4.w};
            float kv[8] = {k4a.x, k4a.y, k4a.z, k4a.w,
                           k4b.x, k4b.y, k4b.z, k4b.w};
            #pragma unroll
            for (int r = 0; r < 4; r++)
                #pragma unroll
                for (int c = 0; c < 8; c++)
                    s[r][c] += qv[r] * kv[c];
        }

        if (kt == qb) {
            #pragma unroll
            for (int r = 0; r < 4; r++)
                #pragma unroll
                for (int c = 0; c < 8; c++)
                    if (c0 + c > r0 + r) s[r][c] = -1e30f;
        }

        #pragma unroll
        for (int r = 0; r < 4; r++) {
            float mx = s[r][0];
            #pragma unroll
            for (int c = 1; c < 8; c++) mx = fmaxf(mx, s[r][c]);
            mx = fmaxf(mx, __shfl_xor_sync(0xffffffffu, mx, 1));
            mx = fmaxf(mx, __shfl_xor_sync(0xffffffffu, mx, 2));
            mx = fmaxf(mx, __shfl_xor_sync(0xffffffffu, mx, 4));
            float mnew = fmaxf(m_i[r], mx);
            float al   = __expf(m_i[r] - mnew);
            float rs = 0.0f;
            #pragma unroll
            for (int c = 0; c < 8; c++) {
                float p = __expf(s[r][c] - mnew);
                s[r][c] = p;
                rs += p;
            }
            rs += __shfl_xor_sync(0xffffffffu, rs, 1);
            rs += __shfl_xor_sync(0xffffffffu, rs, 2);
            rs += __shfl_xor_sync(0xffffffffu, rs, 4);
            l_i[r] = l_i[r] * al + rs;
            m_i[r] = mnew;
            #pragma unroll
            for (int c = 0; c < 8; c++) acc[r][c] *= al;
        }

        __syncthreads();

        #pragma unroll
        for (int c = 0; c < 8; c++)
            #pragma unroll
            for (int r = 0; r < 4; r++)
                sKP[(c0 + c)*68 + r0 + r] = s[r][c];
        __syncthreads();

        #pragma unroll 8
        for (int j = 0; j < 64; j++) {
            float4 p4  = *(const float4*)(sKP + j*68 + r0);
            float4 v4a = *(const float4*)(sV  + j*64 + c0);
            float4 v4b = *(const float4*)(sV  + j*64 + c0 + 4);
            float pv[4] = {p4.x, p4.y, p4.z, p4.w};
            float vv[8] = {v4a.x, v4a.y, v4a.z, v4a.w,
                           v4b.x, v4b.y, v4b.z, v4b.w};
            #pragma unroll
            for (int r = 0; r < 4; r++)
                #pragma unroll
                for (int c = 0; c < 8; c++)
                    acc[r][c] += pv[r] * vv[c];
        }
    }

    const int b = bh / NH, h = bh % NH;
    #pragma unroll
    for (int r = 0; r < 4; r++) {
        float inv = 1.0f / l_i[r];
        int t = qb*64 + r0 + r;
        float* o = g_attn + ((size_t)b*NT + t)*NC + h*DH + c0;
        *(float4*)(o)     = make_float4(acc[r][0]*inv, acc[r][1]*inv,
                                        acc[r][2]*inv, acc[r][3]*inv);
        *(float4*)(o + 4) = make_float4(acc[r][4]*inv, acc[r][5]*inv,
                                        acc[r][6]*inv, acc[r][7]*inv);
    }
}

// ---------------------------------------------------------------------------

extern "C" void kernel_launch(void* const* d_in, const int* in_sizes, int n_in,
                              void* d_out, int out_size)
{
    const float* x  = (const float*)d_in[0];
    const float* Wq = (const float*)d_in[1];
    const float* Wk = (const float*)d_in[2];
    const float* Wv = (const float*)d_in[3];
    const float* Wo = (const float*)d_in[4];
    const float* bo = (const float*)d_in[5];
    float* out = (float*)d_out;

    cudaFuncSetAttribute(attn_kernel,
                         cudaFuncAttributeMaxDynamicSharedMemorySize, ATTN_SMEM);

    mma_gemm_kernel<<< dim3(NC/BN, NM/BM, 3), 256 >>>(
        x, Wq, Wk, Wv, nullptr, nullptr, 0);
    attn_kernel<<< dim3(NT/64, NB*NH), 128, ATTN_SMEM >>>();
    mma_gemm_kernel<<< dim3(NC/BN, NM/BM, 1), 256 >>>(
        nullptr, Wo, nullptr, nullptr, bo, out, 1);
}

// round 5
// speedup vs baseline: 2.2218x; 1.9910x over previous
#include <cuda_runtime.h>
#include <cuda_bf16.h>
#include <cstdint>

// Fixed problem shapes
#define NB 4
#define NT 2048
#define NC 1024
#define NH 16
#define DH 64
#define NM (NB*NT)   // 8192 rows

// Scratch (allocation-free rule: __device__ globals)
__device__ float g_q[(size_t)NB*NH*NT*DH];
__device__ float g_k[(size_t)NB*NH*NT*DH];
__device__ float g_v[(size_t)NB*NH*NT*DH];
__device__ float g_attn[(size_t)NB*NT*NC];

// bf16 hi/lo split, packed as (x:low half, y:high half)
__device__ __forceinline__ void split_pack(float x, float y,
                                           uint32_t &hi, uint32_t &lo) {
    __nv_bfloat16 hx = __float2bfloat16_rn(x), hy = __float2bfloat16_rn(y);
    float fx = __bfloat162float(hx), fy = __bfloat162float(hy);
    __nv_bfloat16 lx = __float2bfloat16_rn(x - fx), ly = __float2bfloat16_rn(y - fy);
    hi = ((uint32_t)__bfloat16_as_ushort(hy) << 16) | __bfloat16_as_ushort(hx);
    lo = ((uint32_t)__bfloat16_as_ushort(ly) << 16) | __bfloat16_as_ushort(lx);
}

#define MMA_BF16(d, a0,a1,a2,a3, b0,b1) \
    asm volatile("mma.sync.aligned.m16n8k16.row.col.f32.bf16.bf16.f32 " \
        "{%0,%1,%2,%3}, {%4,%5,%6,%7}, {%8,%9}, {%0,%1,%2,%3};" \
        : "+f"(d[0]), "+f"(d[1]), "+f"(d[2]), "+f"(d[3]) \
        : "r"(a0), "r"(a1), "r"(a2), "r"(a3), "r"(b0), "r"(b1))

__device__ __forceinline__ uint32_t ldu32(const unsigned short* p) {
    return *(const uint32_t*)p;
}

// ===========================================================================
// 3xBF16 tensor GEMM:  C[M,N] = A[M,K] * B[N,K]^T  (K-major both)
// Block 128x128x16, 256 thr, 8 warps (2x4), warp tile 64x32, k16 MMAs.
// mode 0: QKV projection (z selects W; scatter out to [B,H,T,DH])
// mode 1: output projection (+bias, natural [M,N])
// ===========================================================================
#define BM 128
#define BN 128
#define BK 16
#define GLDS 24   // padded bf16 stride (16 + 8)

__global__ __launch_bounds__(256) void mma_gemm_kernel(
    const float* __restrict__ x,
    const float* __restrict__ Wq,
    const float* __restrict__ Wk,
    const float* __restrict__ Wv,
    const float* __restrict__ bias,
    float* __restrict__ Cout,
    int mode)
{
    __shared__ unsigned short sAh[BM*GLDS], sAl[BM*GLDS];
    __shared__ unsigned short sBh[BN*GLDS], sBl[BN*GLDS];

    const int tid  = threadIdx.x;
    const int wid  = tid >> 5;
    const int lane = tid & 31;
    const int warp_m = wid >> 2;      // 0..1
    const int warp_n = wid & 3;       // 0..3
    const int qr = lane >> 2;         // 0..7
    const int qc = lane & 3;          // 0..3

    const int row0 = blockIdx.y * BM;
    const int col0 = blockIdx.x * BN;

    const float* A;
    const float* W;
    float* outq = 0;
    if (mode == 0) {
        A = x;
        if (blockIdx.z == 0)      { W = Wq; outq = g_q; }
        else if (blockIdx.z == 1) { W = Wk; outq = g_k; }
        else                      { W = Wv; outq = g_v; }
    } else {
        A = g_attn;
        W = Wq;   // Wo in slot 0
    }

    const int lr = tid >> 1;
    const int lc = (tid & 1) * 8;
    const float* Ap = A + (size_t)(row0 + lr) * NC + lc;
    const float* Bp = W + (size_t)(col0 + lr) * NC + lc;

    float acc[4][4][4] = {};

    float4 pa0 = *(const float4*)(Ap);
    float4 pa1 = *(const float4*)(Ap + 4);
    float4 pb0 = *(const float4*)(Bp);
    float4 pb1 = *(const float4*)(Bp + 4);
    Ap += BK; Bp += BK;

    const int so = lr*GLDS + lc;
    const int kb = qc*2;   // bf16 col within k16

    for (int c = 0; c < NC/BK; c++) {
        uint32_t h, l;
        split_pack(pa0.x, pa0.y, h, l); *(uint32_t*)&sAh[so]   = h; *(uint32_t*)&sAl[so]   = l;
        split_pack(pa0.z, pa0.w, h, l); *(uint32_t*)&sAh[so+2] = h; *(uint32_t*)&sAl[so+2] = l;
        split_pack(pa1.x, pa1.y, h, l); *(uint32_t*)&sAh[so+4] = h; *(uint32_t*)&sAl[so+4] = l;
        split_pack(pa1.z, pa1.w, h, l); *(uint32_t*)&sAh[so+6] = h; *(uint32_t*)&sAl[so+6] = l;
        split_pack(pb0.x, pb0.y, h, l); *(uint32_t*)&sBh[so]   = h; *(uint32_t*)&sBl[so]   = l;
        split_pack(pb0.z, pb0.w, h, l); *(uint32_t*)&sBh[so+2] = h; *(uint32_t*)&sBl[so+2] = l;
        split_pack(pb1.x, pb1.y, h, l); *(uint32_t*)&sBh[so+4] = h; *(uint32_t*)&sBl[so+4] = l;
        split_pack(pb1.z, pb1.w, h, l); *(uint32_t*)&sBh[so+6] = h; *(uint32_t*)&sBl[so+6] = l;
        __syncthreads();

        if (c + 1 < NC/BK) {
            pa0 = *(const float4*)(Ap);
            pa1 = *(const float4*)(Ap + 4);
            pb0 = *(const float4*)(Bp);
            pb1 = *(const float4*)(Bp + 4);
            Ap += BK; Bp += BK;
        }

        uint32_t Ah[4][4], Al[4][4], Bh[4][2], Bl[4][2];
        #pragma unroll
        for (int mi = 0; mi < 4; mi++) {
            const int ar = warp_m*64 + mi*16 + qr;
            Ah[mi][0] = ldu32(&sAh[ar*GLDS + kb]);
            Ah[mi][1] = ldu32(&sAh[(ar+8)*GLDS + kb]);
            Ah[mi][2] = ldu32(&sAh[ar*GLDS + kb + 8]);
            Ah[mi][3] = ldu32(&sAh[(ar+8)*GLDS + kb + 8]);
            Al[mi][0] = ldu32(&sAl[ar*GLDS + kb]);
            Al[mi][1] = ldu32(&sAl[(ar+8)*GLDS + kb]);
            Al[mi][2] = ldu32(&sAl[ar*GLDS + kb + 8]);
            Al[mi][3] = ldu32(&sAl[(ar+8)*GLDS + kb + 8]);
        }
        #pragma unroll
        for (int ni = 0; ni < 4; ni++) {
            const int br = warp_n*32 + ni*8 + qr;
            Bh[ni][0] = ldu32(&sBh[br*GLDS + kb]);
            Bh[ni][1] = ldu32(&sBh[br*GLDS + kb + 8]);
            Bl[ni][0] = ldu32(&sBl[br*GLDS + kb]);
            Bl[ni][1] = ldu32(&sBl[br*GLDS + kb + 8]);
        }
        #pragma unroll
        for (int mi = 0; mi < 4; mi++)
            #pragma unroll
            for (int ni = 0; ni < 4; ni++) {
                MMA_BF16(acc[mi][ni], Ah[mi][0],Ah[mi][1],Ah[mi][2],Ah[mi][3], Bh[ni][0],Bh[ni][1]);
                MMA_BF16(acc[mi][ni], Al[mi][0],Al[mi][1],Al[mi][2],Al[mi][3], Bh[ni][0],Bh[ni][1]);
                MMA_BF16(acc[mi][ni], Ah[mi][0],Ah[mi][1],Ah[mi][2],Ah[mi][3], Bl[ni][0],Bl[ni][1]);
            }
        __syncthreads();
    }

    #pragma unroll
    for (int mi = 0; mi < 4; mi++) {
        const int m0 = row0 + warp_m*64 + mi*16 + qr;
        #pragma unroll
        for (int ni = 0; ni < 4; ni++) {
            const int n = col0 + warp_n*32 + ni*8 + qc*2;
            if (mode == 0) {
                const int h = n >> 6, d = n & 63;
                #pragma unroll
                for (int half = 0; half < 2; half++) {
                    const int m = m0 + half*8;
                    const int b = m >> 11, t = m & (NT-1);
                    float* o = outq + (((size_t)b*NH + h)*NT + t)*DH + d;
                    *(float2*)o = make_float2(acc[mi][ni][half*2], acc[mi][ni][half*2+1]);
                }
            } else {
                const float2 bv = *(const float2*)(bias + n);
                #pragma unroll
                for (int half = 0; half < 2; half++) {
                    const int m = m0 + half*8;
                    float* o = Cout + (size_t)m*NC + n;
                    *(float2*)o = make_float2(acc[mi][ni][half*2] + bv.x,
                                              acc[mi][ni][half*2+1] + bv.y);
                }
            }
        }
    }
}

// ===========================================================================
// Tensor-core causal flash attention (3xBF16 mma.sync).
// Block = 128 query rows of one (b,h). Bc=64. 256 thr, 8 warps x 16 rows.
// smem (ushort units): Qh Ql [128][72], Kh Kl [64][72] (K rows=key,cols=d),
//                      Vh Vl [64][72] (rows=d, cols=key), Ph Pl [128][72].
// ===========================================================================
#define ALDS 72
#define AQ_OFF   0
#define AQL_OFF  (128*ALDS)
#define AKH_OFF  (2*128*ALDS)
#define AKL_OFF  (AKH_OFF + 64*ALDS)
#define AVH_OFF  (AKL_OFF + 64*ALDS)
#define AVL_OFF  (AVH_OFF + 64*ALDS)
#define APH_OFF  (AVL_OFF + 64*ALDS)
#define APL_OFF  (APH_OFF + 128*ALDS)
#define ATT_USH  (APL_OFF + 128*ALDS)
#define ATT_SMEM (ATT_USH * 2)

__global__ __launch_bounds__(256) void attn_mma_kernel()
{
    extern __shared__ unsigned short su[];
    unsigned short* sQh = su + AQ_OFF;
    unsigned short* sQl = su + AQL_OFF;
    unsigned short* sKh = su + AKH_OFF;
    unsigned short* sKl = su + AKL_OFF;
    unsigned short* sVh = su + AVH_OFF;
    unsigned short* sVl = su + AVL_OFF;
    unsigned short* sPh = su + APH_OFF;
    unsigned short* sPl = su + APL_OFF;

    const int tid  = threadIdx.x;
    const int wid  = tid >> 5;
    const int lane = tid & 31;
    const int qr = lane >> 2;   // 0..7
    const int qc = lane & 3;    // 0..3
    const int r0 = wid * 16;    // warp's query rows (within 128-tile)

    const int qt = gridDim.x - 1 - blockIdx.x;   // heavy blocks first
    const int bh = blockIdx.y;

    // ---- load Q (scaled by sqrt(HS)=8), split to bf16 hi/lo ----
    {
        const int lrq = tid >> 1;           // 0..127
        const int lcq = (tid & 1) * 32;
        const float* Qg = g_q + ((size_t)bh*NT + (size_t)qt*128 + lrq) * DH + lcq;
        #pragma unroll
        for (int i = 0; i < 8; i++) {
            float4 v = *(const float4*)(Qg + i*4);
            uint32_t h, l;
            split_pack(v.x*8.0f, v.y*8.0f, h, l);
            *(uint32_t*)&sQh[lrq*ALDS + lcq + i*4]     = h;
            *(uint32_t*)&sQl[lrq*ALDS + lcq + i*4]     = l;
            split_pack(v.z*8.0f, v.w*8.0f, h, l);
            *(uint32_t*)&sQh[lrq*ALDS + lcq + i*4 + 2] = h;
            *(uint32_t*)&sQl[lrq*ALDS + lcq + i*4 + 2] = l;
        }
    }

    float m_a = -1e30f, m_b = -1e30f, l_a = 0.0f, l_b = 0.0f;
    float O[8][4] = {};   // 8 d-tiles x c-frag

    const int lrk = tid >> 2;            // 0..63 (key row / v row)
    const int lck = (tid & 3) * 16;      // col base (d)

    const int n_kv = 2*qt + 2;
    for (int kt = 0; kt < n_kv; kt++) {
        // prefetch K,V tile into regs (issue before barrier)
        const float* Kg = g_k + ((size_t)bh*NT + (size_t)kt*64 + lrk) * DH + lck;
        const float* Vg = g_v + ((size_t)bh*NT + (size_t)kt*64 + lrk) * DH + lck;
        float4 kv[4], vv[4];
        #pragma unroll
        for (int i = 0; i < 4; i++) {
            kv[i] = *(const float4*)(Kg + i*4);
            vv[i] = *(const float4*)(Vg + i*4);
        }
        __syncthreads();   // prev tile's MMAs/LDS done with K,V buffers

        // store K (row=key, col=d) and V transposed (row=d, col=key)
        #pragma unroll
        for (int i = 0; i < 4; i++) {
            uint32_t h, l;
            split_pack(kv[i].x, kv[i].y, h, l);
            *(uint32_t*)&sKh[lrk*ALDS + lck + i*4]     = h;
            *(uint32_t*)&sKl[lrk*ALDS + lck + i*4]     = l;
            split_pack(kv[i].z, kv[i].w, h, l);
            *(uint32_t*)&sKh[lrk*ALDS + lck + i*4 + 2] = h;
            *(uint32_t*)&sKl[lrk*ALDS + lck + i*4 + 2] = l;
            const float vf[4] = {vv[i].x, vv[i].y, vv[i].z, vv[i].w};
            #pragma unroll
            for (int e = 0; e < 4; e++) {
                const int d = lck + i*4 + e;
                __nv_bfloat16 bh16 = __float2bfloat16_rn(vf[e]);
                float fh = __bfloat162float(bh16);
                sVh[d*ALDS + lrk] = __bfloat16_as_ushort(bh16);
                sVl[d*ALDS + lrk] = __bfloat16_as_ushort(__float2bfloat16_rn(vf[e] - fh));
            }
        }
        __syncthreads();

        // ---- S = Q K^T (3xBF16), warp rows r0..r0+15, all 64 key cols ----
        float S[8][4] = {};
        #pragma unroll
        for (int ks = 0; ks < 4; ks++) {
            const int kb = ks*16 + qc*2;
            const int ar = r0 + qr;
            uint32_t a0 = ldu32(&sQh[ar*ALDS + kb]);
            uint32_t a1 = ldu32(&sQh[(ar+8)*ALDS + kb]);
            uint32_t a2 = ldu32(&sQh[ar*ALDS + kb + 8]);
            uint32_t a3 = ldu32(&sQh[(ar+8)*ALDS + kb + 8]);
            uint32_t c0 = ldu32(&sQl[ar*ALDS + kb]);
            uint32_t c1 = ldu32(&sQl[(ar+8)*ALDS + kb]);
            uint32_t c2 = ldu32(&sQl[ar*ALDS + kb + 8]);
            uint32_t c3 = ldu32(&sQl[(ar+8)*ALDS + kb + 8]);
            #pragma unroll
            for (int nt = 0; nt < 8; nt++) {
                const int br = nt*8 + qr;
                uint32_t b0 = ldu32(&sKh[br*ALDS + kb]);
                uint32_t b1 = ldu32(&sKh[br*ALDS + kb + 8]);
                uint32_t d0 = ldu32(&sKl[br*ALDS + kb]);
                uint32_t d1 = ldu32(&sKl[br*ALDS + kb + 8]);
                MMA_BF16(S[nt], a0,a1,a2,a3, b0,b1);
                MMA_BF16(S[nt], c0,c1,c2,c3, b0,b1);
                MMA_BF16(S[nt], a0,a1,a2,a3, d0,d1);
            }
        }

        // ---- causal mask (only diagonal-crossing tiles) ----
        if (kt >= 2*qt) {
            const int ia = qt*128 + r0 + qr;
            #pragma unroll
            for (int nt = 0; nt < 8; nt++) {
                const int j0g = kt*64 + nt*8 + qc*2;
                if (j0g   > ia)   S[nt][0] = -1e30f;
                if (j0g+1 > ia)   S[nt][1] = -1e30f;
                if (j0g   > ia+8) S[nt][2] = -1e30f;
                if (j0g+1 > ia+8) S[nt][3] = -1e30f;
            }
        }

        // ---- online softmax (rows qr, qr+8; stats shared across quad) ----
        float mxa = -1e30f, mxb = -1e30f;
        #pragma unroll
        for (int nt = 0; nt < 8; nt++) {
            mxa = fmaxf(mxa, fmaxf(S[nt][0], S[nt][1]));
            mxb = fmaxf(mxb, fmaxf(S[nt][2], S[nt][3]));
        }
        mxa = fmaxf(mxa, __shfl_xor_sync(0xffffffffu, mxa, 1));
        mxa = fmaxf(mxa, __shfl_xor_sync(0xffffffffu, mxa, 2));
        mxb = fmaxf(mxb, __shfl_xor_sync(0xffffffffu, mxb, 1));
        mxb = fmaxf(mxb, __shfl_xor_sync(0xffffffffu, mxb, 2));
        const float mna = fmaxf(m_a, mxa), mnb = fmaxf(m_b, mxb);
        const float ala = __expf(m_a - mna), alb = __expf(m_b - mnb);
        float rsa = 0.0f, rsb = 0.0f;
        #pragma unroll
        for (int nt = 0; nt < 8; nt++) {
            S[nt][0] = __expf(S[nt][0] - mna);
            S[nt][1] = __expf(S[nt][1] - mna);
            S[nt][2] = __expf(S[nt][2] - mnb);
            S[nt][3] = __expf(S[nt][3] - mnb);
            rsa += S[nt][0] + S[nt][1];
            rsb += S[nt][2] + S[nt][3];
        }
        rsa += __shfl_xor_sync(0xffffffffu, rsa, 1);
        rsa += __shfl_xor_sync(0xffffffffu, rsa, 2);
        rsb += __shfl_xor_sync(0xffffffffu, rsb, 1);
        rsb += __shfl_xor_sync(0xffffffffu, rsb, 2);
        l_a = l_a * ala + rsa;  m_a = mna;
        l_b = l_b * alb + rsb;  m_b = mnb;
        #pragma unroll
        for (int nt = 0; nt < 8; nt++) {
            O[nt][0] *= ala; O[nt][1] *= ala;
            O[nt][2] *= alb; O[nt][3] *= alb;
        }

        // ---- write P (warp-private rows), split bf16 hi/lo ----
        #pragma unroll
        for (int nt = 0; nt < 8; nt++) {
            uint32_t h, l;
            split_pack(S[nt][0], S[nt][1], h, l);
            *(uint32_t*)&sPh[(r0+qr)*ALDS + nt*8 + qc*2]   = h;
            *(uint32_t*)&sPl[(r0+qr)*ALDS + nt*8 + qc*2]   = l;
            split_pack(S[nt][2], S[nt][3], h, l);
            *(uint32_t*)&sPh[(r0+qr+8)*ALDS + nt*8 + qc*2] = h;
            *(uint32_t*)&sPl[(r0+qr+8)*ALDS + nt*8 + qc*2] = l;
        }
        __syncwarp();

        // ---- O += P V  (P split x V split, 3 terms) ----
        #pragma unroll
        for (int ks = 0; ks < 4; ks++) {
            const int kb = ks*16 + qc*2;
            const int ar = r0 + qr;
            uint32_t a0 = ldu32(&sPh[ar*ALDS + kb]);
            uint32_t a1 = ldu32(&sPh[(ar+8)*ALDS + kb]);
            uint32_t a2 = ldu32(&sPh[ar*ALDS + kb + 8]);
            uint32_t a3 = ldu32(&sPh[(ar+8)*ALDS + kb + 8]);
            uint32_t c0 = ldu32(&sPl[ar*ALDS + kb]);
            uint32_t c1 = ldu32(&sPl[(ar+8)*ALDS + kb]);
            uint32_t c2 = ldu32(&sPl[ar*ALDS + kb + 8]);
            uint32_t c3 = ldu32(&sPl[(ar+8)*ALDS + kb + 8]);
            #pragma unroll
            for (int nt = 0; nt < 8; nt++) {
                const int br = nt*8 + qr;     // d row of Vt
                uint32_t b0 = ldu32(&sVh[br*ALDS + kb]);
                uint32_t b1 = ldu32(&sVh[br*ALDS + kb + 8]);
                uint32_t d0 = ldu32(&sVl[br*ALDS + kb]);
                uint32_t d1 = ldu32(&sVl[br*ALDS + kb + 8]);
                MMA_BF16(O[nt], a0,a1,a2,a3, b0,b1);
                MMA_BF16(O[nt], c0,c1,c2,c3, b0,b1);
                MMA_BF16(O[nt], a0,a1,a2,a3, d0,d1);
            }
        }
    }

    // ---- epilogue: normalize, write [B,T,H*HS] ----
    const int b = bh / NH, h = bh % NH;
    const float inva = 1.0f / l_a, invb = 1.0f / l_b;
    const int ta = qt*128 + r0 + qr;
    #pragma unroll
    for (int nt = 0; nt < 8; nt++) {
        const int d = nt*8 + qc*2;
        float* oa = g_attn + ((size_t)b*NT + ta)*NC + h*DH + d;
        float* ob = g_attn + ((size_t)b*NT + ta + 8)*NC + h*DH + d;
        *(float2*)oa = make_float2(O[nt][0]*inva, O[nt][1]*inva);
        *(float2*)ob = make_float2(O[nt][2]*invb, O[nt][3]*invb);
    }
}

// ---------------------------------------------------------------------------

extern "C" void kernel_launch(void* const* d_in, const int* in_sizes, int n_in,
                              void* d_out, int out_size)
{
    const float* x  = (const float*)d_in[0];
    const float* Wq = (const float*)d_in[1];
    const float* Wk = (const float*)d_in[2];
    const float* Wv = (const float*)d_in[3];
    const float* Wo = (const float*)d_in[4];
    const float* bo = (const float*)d_in[5];
    float* out = (float*)d_out;

    cudaFuncSetAttribute(attn_mma_kernel,
                         cudaFuncAttributeMaxDynamicSharedMemorySize, ATT_SMEM);

    mma_gemm_kernel<<< dim3(NC/BN, NM/BM, 3), 256 >>>(
        x, Wq, Wk, Wv, nullptr, nullptr, 0);
    attn_mma_kernel<<< dim3(NT/128, NB*NH), 256, ATT_SMEM >>>();
    mma_gemm_kernel<<< dim3(NC/BN, NM/BM, 1), 256 >>>(
        nullptr, Wo, nullptr, nullptr, bo, out, 1);
}

// round 6
// speedup vs baseline: 2.6660x; 1.1999x over previous
#include <cuda_runtime.h>
#include <cuda_bf16.h>
#include <cstdint>

// Fixed problem shapes
#define NB 4
#define NT 2048
#define NC 1024
#define NH 16
#define DH 64
#define NM (NB*NT)   // 8192 rows

typedef unsigned short ush;

// Scratch (allocation-free rule: __device__ globals)
__device__ ush g_xh[(size_t)NM*NC], g_xl[(size_t)NM*NC];
__device__ ush g_wh[(size_t)4*NC*NC], g_wl[(size_t)4*NC*NC];
__device__ ush g_qh[(size_t)NB*NH*NT*DH], g_ql[(size_t)NB*NH*NT*DH];
__device__ ush g_kh[(size_t)NB*NH*NT*DH], g_kl[(size_t)NB*NH*NT*DH];
__device__ ush g_vh[(size_t)NB*NH*NT*DH], g_vl[(size_t)NB*NH*NT*DH];
__device__ ush g_ah[(size_t)NM*NC], g_al[(size_t)NM*NC];

// bf16 hi/lo split of a float pair, packed (x: low half, y: high half)
__device__ __forceinline__ void split_pack(float x, float y,
                                           uint32_t &hi, uint32_t &lo) {
    __nv_bfloat16 hx = __float2bfloat16_rn(x), hy = __float2bfloat16_rn(y);
    float fx = __bfloat162float(hx), fy = __bfloat162float(hy);
    __nv_bfloat16 lx = __float2bfloat16_rn(x - fx), ly = __float2bfloat16_rn(y - fy);
    hi = ((uint32_t)__bfloat16_as_ushort(hy) << 16) | __bfloat16_as_ushort(hx);
    lo = ((uint32_t)__bfloat16_as_ushort(ly) << 16) | __bfloat16_as_ushort(lx);
}

#define MMA_BF16(d, a0,a1,a2,a3, b0,b1) \
    asm volatile("mma.sync.aligned.m16n8k16.row.col.f32.bf16.bf16.f32 " \
        "{%0,%1,%2,%3}, {%4,%5,%6,%7}, {%8,%9}, {%0,%1,%2,%3};" \
        : "+f"(d[0]), "+f"(d[1]), "+f"(d[2]), "+f"(d[3]) \
        : "r"(a0), "r"(a1), "r"(a2), "r"(a3), "r"(b0), "r"(b1))

__device__ __forceinline__ uint32_t ldu32(const ush* p) { return *(const uint32_t*)p; }

#define CP16(saddr, gptr) \
    asm volatile("cp.async.cg.shared.global [%0], [%1], 16;" \
                 :: "r"(saddr), "l"(gptr) : "memory")
#define CP_COMMIT() asm volatile("cp.async.commit_group;" ::: "memory")
#define CP_WAIT1()  asm volatile("cp.async.wait_group 1;" ::: "memory")
#define CP_WAIT0()  asm volatile("cp.async.wait_group 0;" ::: "memory")

// ===========================================================================
// One-shot fp32 -> bf16 hi/lo conversion of x and all weights (Wq pre-scaled
// by sqrt(HS)=8, folding the reference's q*k*8 into the Q projection).
// ===========================================================================
#define N4X ((size_t)NM*NC/4)    // 2097152 float4s
#define N4W ((size_t)NC*NC/4)    // 262144 float4s per weight

__global__ __launch_bounds__(256) void convert_kernel(
    const float* __restrict__ x,  const float* __restrict__ Wq,
    const float* __restrict__ Wk, const float* __restrict__ Wv,
    const float* __restrict__ Wo)
{
    const size_t i = (size_t)blockIdx.x * blockDim.x + threadIdx.x;
    const float* src;
    ush *dh, *dl;
    float sc = 1.0f;
    if (i < N4X) {
        src = x + i*4; dh = g_xh + i*4; dl = g_xl + i*4;
    } else {
        size_t j = i - N4X;
        size_t w = j / N4W, r = j % N4W;
        const float* ws[4] = {Wq, Wk, Wv, Wo};
        src = ws[w] + r*4;
        dh = g_wh + w*(size_t)NC*NC + r*4;
        dl = g_wl + w*(size_t)NC*NC + r*4;
        if (w == 0) sc = 8.0f;
    }
    float4 v = *(const float4*)src;
    uint32_t h0, l0, h1, l1;
    split_pack(v.x*sc, v.y*sc, h0, l0);
    split_pack(v.z*sc, v.w*sc, h1, l1);
    *(uint32_t*)(dh)   = h0;  *(uint32_t*)(dh+2) = h1;
    *(uint32_t*)(dl)   = l0;  *(uint32_t*)(dl+2) = l1;
}

// ===========================================================================
// 3xBF16 tensor GEMM, pre-converted operands, cp.async double buffer.
// C[M,N] = A[M,K]*B[N,K]^T. Block 128x128x32, 256 thr, 8 warps (2x4).
// mode 0: QKV (z selects W plane; output written split hi/lo, [B,H,T,DH])
// mode 1: oproj (+bias, fp32 out [M,N])
// ===========================================================================
#define BM 128
#define BN 128
#define BK2 32
#define NCHUNK (NC/BK2)   // 32
#define SST 40            // ushort row stride (32 + 8 pad)
#define PL (128*SST)      // plane size in ushorts: 5120
#define GEMM_SMEM (2*4*PL*2)   // 2 stages x 4 planes x 5120 ush x 2B = 81920

__global__ __launch_bounds__(256) void gemm_bf16(
    const float* __restrict__ bias,
    float* __restrict__ Cout,
    int mode)
{
    extern __shared__ ush sm[];

    const int tid  = threadIdx.x;
    const int wid  = tid >> 5;
    const int lane = tid & 31;
    const int warp_m = wid >> 2;      // 0..1
    const int warp_n = wid & 3;       // 0..3
    const int qr = lane >> 2;         // 0..7
    const int qc = lane & 3;          // 0..3

    const int row0 = blockIdx.y * BM;
    const int col0 = blockIdx.x * BN;

    const ush *Ah, *Al, *Wh, *Wl;
    ush *outh = 0, *outl = 0;
    if (mode == 0) {
        Ah = g_xh; Al = g_xl;
        const size_t wo = (size_t)blockIdx.z * NC * NC;
        Wh = g_wh + wo; Wl = g_wl + wo;
        if (blockIdx.z == 0)      { outh = g_qh; outl = g_ql; }
        else if (blockIdx.z == 1) { outh = g_kh; outl = g_kl; }
        else                      { outh = g_vh; outl = g_vl; }
    } else {
        Ah = g_ah; Al = g_al;
        Wh = g_wh + (size_t)3*NC*NC; Wl = g_wl + (size_t)3*NC*NC;
    }

    // loader: thread t -> row t>>1, 32B half (t&1)
    const int r  = tid >> 1;
    const int hf = (tid & 1) * 16;    // ushort offset
    const ush* gAh = Ah + (size_t)(row0 + r)*NC + hf;
    const ush* gAl = Al + (size_t)(row0 + r)*NC + hf;
    const ush* gBh = Wh + (size_t)(col0 + r)*NC + hf;
    const ush* gBl = Wl + (size_t)(col0 + r)*NC + hf;
    const uint32_t sbase = (uint32_t)__cvta_generic_to_shared(sm);
    const uint32_t soff = (uint32_t)(r*SST + hf) * 2;   // bytes

    auto load_stage = [&](int c, int s) {
        const uint32_t st = sbase + (uint32_t)s*4*PL*2 + soff;
        const int g = c * BK2;
        CP16(st,            gAh + g);
        CP16(st + 16,       gAh + g + 8);
        CP16(st + PL*2,     gAl + g);
        CP16(st + PL*2+16,  gAl + g + 8);
        CP16(st + 2*PL*2,   gBh + g);
        CP16(st + 2*PL*2+16,gBh + g + 8);
        CP16(st + 3*PL*2,   gBl + g);
        CP16(st + 3*PL*2+16,gBl + g + 8);
        CP_COMMIT();
    };

    float acc[4][4][4] = {};

    load_stage(0, 0);
    load_stage(1, 1);

    for (int c = 0; c < NCHUNK; c++) {
        if (c == NCHUNK-1) { CP_WAIT0(); } else { CP_WAIT1(); }
        __syncthreads();

        const ush* sAh = sm + (c&1)*4*PL;
        const ush* sAl = sAh + PL;
        const ush* sBh = sAh + 2*PL;
        const ush* sBl = sAh + 3*PL;

        #pragma unroll
        for (int kk = 0; kk < 2; kk++) {
            const int kb = kk*16 + qc*2;
            uint32_t A0[4][4], A1[4][4], B0[4][2], B1[4][2];
            #pragma unroll
            for (int mi = 0; mi < 4; mi++) {
                const int ar = warp_m*64 + mi*16 + qr;
                A0[mi][0] = ldu32(&sAh[ar*SST + kb]);
                A0[mi][1] = ldu32(&sAh[(ar+8)*SST + kb]);
                A0[mi][2] = ldu32(&sAh[ar*SST + kb + 8]);
                A0[mi][3] = ldu32(&sAh[(ar+8)*SST + kb + 8]);
                A1[mi][0] = ldu32(&sAl[ar*SST + kb]);
                A1[mi][1] = ldu32(&sAl[(ar+8)*SST + kb]);
                A1[mi][2] = ldu32(&sAl[ar*SST + kb + 8]);
                A1[mi][3] = ldu32(&sAl[(ar+8)*SST + kb + 8]);
            }
            #pragma unroll
            for (int ni = 0; ni < 4; ni++) {
                const int br = warp_n*32 + ni*8 + qr;
                B0[ni][0] = ldu32(&sBh[br*SST + kb]);
                B0[ni][1] = ldu32(&sBh[br*SST + kb + 8]);
                B1[ni][0] = ldu32(&sBl[br*SST + kb]);
                B1[ni][1] = ldu32(&sBl[br*SST + kb + 8]);
            }
            #pragma unroll
            for (int mi = 0; mi < 4; mi++)
                #pragma unroll
                for (int ni = 0; ni < 4; ni++) {
                    MMA_BF16(acc[mi][ni], A0[mi][0],A0[mi][1],A0[mi][2],A0[mi][3], B0[ni][0],B0[ni][1]);
                    MMA_BF16(acc[mi][ni], A1[mi][0],A1[mi][1],A1[mi][2],A1[mi][3], B0[ni][0],B0[ni][1]);
                    MMA_BF16(acc[mi][ni], A0[mi][0],A0[mi][1],A0[mi][2],A0[mi][3], B1[ni][0],B1[ni][1]);
                }
        }
        __syncthreads();
        if (c + 2 < NCHUNK) load_stage(c + 2, c & 1);
    }

    // Epilogue
    #pragma unroll
    for (int mi = 0; mi < 4; mi++) {
        const int m0 = row0 + warp_m*64 + mi*16 + qr;
        #pragma unroll
        for (int ni = 0; ni < 4; ni++) {
            const int n = col0 + warp_n*32 + ni*8 + qc*2;
            if (mode == 0) {
                const int h = n >> 6, d = n & 63;
                #pragma unroll
                for (int half = 0; half < 2; half++) {
                    const int m = m0 + half*8;
                    const int b = m >> 11, t = m & (NT-1);
                    const size_t idx = (((size_t)b*NH + h)*NT + t)*DH + d;
                    uint32_t hh, ll;
                    split_pack(acc[mi][ni][half*2], acc[mi][ni][half*2+1], hh, ll);
                    *(uint32_t*)&outh[idx] = hh;
                    *(uint32_t*)&outl[idx] = ll;
                }
            } else {
                const float2 bv = *(const float2*)(bias + n);
                #pragma unroll
                for (int half = 0; half < 2; half++) {
                    const int m = m0 + half*8;
                    float* o = Cout + (size_t)m*NC + n;
                    *(float2*)o = make_float2(acc[mi][ni][half*2] + bv.x,
                                              acc[mi][ni][half*2+1] + bv.y);
                }
            }
        }
    }
}

// ===========================================================================
// Tensor-core causal flash attention (3xBF16), pre-split q/k/v inputs.
// Block = 128 query rows of one (b,h). Bc=64. 256 thr, 8 warps x 16 rows.
// Output written split hi/lo into g_ah/g_al ([B,T,H*HS] layout) for oproj.
// ===========================================================================
#define ALDS 72
#define AQ_OFF   0
#define AQL_OFF  (128*ALDS)
#define AKH_OFF  (2*128*ALDS)
#define AKL_OFF  (AKH_OFF + 64*ALDS)
#define AVH_OFF  (AKL_OFF + 64*ALDS)
#define AVL_OFF  (AVH_OFF + 64*ALDS)
#define APH_OFF  (AVL_OFF + 64*ALDS)
#define APL_OFF  (APH_OFF + 128*ALDS)
#define ATT_USH  (APL_OFF + 128*ALDS)
#define ATT_SMEM (ATT_USH * 2)

__global__ __launch_bounds__(256) void attn_mma_kernel()
{
    extern __shared__ ush su[];
    ush* sQh = su + AQ_OFF;
    ush* sQl = su + AQL_OFF;
    ush* sKh = su + AKH_OFF;
    ush* sKl = su + AKL_OFF;
    ush* sVh = su + AVH_OFF;
    ush* sVl = su + AVL_OFF;
    ush* sPh = su + APH_OFF;
    ush* sPl = su + APL_OFF;

    const int tid  = threadIdx.x;
    const int wid  = tid >> 5;
    const int lane = tid & 31;
    const int qr = lane >> 2;
    const int qc = lane & 3;
    const int r0 = wid * 16;

    const int qt = gridDim.x - 1 - blockIdx.x;
    const int bh = blockIdx.y;

    // Q tile (already scaled via Wq*8 at convert time)
    {
        const int lrq = tid >> 1;
        const int lcq = (tid & 1) * 32;
        const size_t qoff = ((size_t)bh*NT + (size_t)qt*128 + lrq)*DH + lcq;
        #pragma unroll
        for (int i = 0; i < 4; i++) {
            *(uint4*)&sQh[lrq*ALDS + lcq + i*8] = *(const uint4*)(g_qh + qoff + i*8);
            *(uint4*)&sQl[lrq*ALDS + lcq + i*8] = *(const uint4*)(g_ql + qoff + i*8);
        }
    }

    float m_a = -1e30f, m_b = -1e30f, l_a = 0.0f, l_b = 0.0f;
    float O[8][4] = {};

    const int lrk = tid >> 2;         // 0..63
    const int lck = (tid & 3) * 16;   // d base

    const int n_kv = 2*qt + 2;
    for (int kt = 0; kt < n_kv; kt++) {
        const size_t koff = ((size_t)bh*NT + (size_t)kt*64 + lrk)*DH + lck;
        uint4 kh0 = *(const uint4*)(g_kh + koff);
        uint4 kh1 = *(const uint4*)(g_kh + koff + 8);
        uint4 kl0 = *(const uint4*)(g_kl + koff);
        uint4 kl1 = *(const uint4*)(g_kl + koff + 8);
        uint4 vh0 = *(const uint4*)(g_vh + koff);
        uint4 vh1 = *(const uint4*)(g_vh + koff + 8);
        uint4 vl0 = *(const uint4*)(g_vl + koff);
        uint4 vl1 = *(const uint4*)(g_vl + koff + 8);
        __syncthreads();   // prev tile consumers done

        *(uint4*)&sKh[lrk*ALDS + lck]     = kh0;
        *(uint4*)&sKh[lrk*ALDS + lck + 8] = kh1;
        *(uint4*)&sKl[lrk*ALDS + lck]     = kl0;
        *(uint4*)&sKl[lrk*ALDS + lck + 8] = kl1;
        {   // V transposed: row=d, col=key
            const ush* ph0 = (const ush*)&vh0;
            const ush* ph1 = (const ush*)&vh1;
            const ush* pl0 = (const ush*)&vl0;
            const ush* pl1 = (const ush*)&vl1;
            #pragma unroll
            for (int e = 0; e < 8; e++) {
                sVh[(lck+e)*ALDS + lrk]   = ph0[e];
                sVh[(lck+8+e)*ALDS + lrk] = ph1[e];
                sVl[(lck+e)*ALDS + lrk]   = pl0[e];
                sVl[(lck+8+e)*ALDS + lrk] = pl1[e];
            }
        }
        __syncthreads();

        // S = Q K^T
        float S[8][4] = {};
        #pragma unroll
        for (int ks = 0; ks < 4; ks++) {
            const int kb = ks*16 + qc*2;
            const int ar = r0 + qr;
            uint32_t a0 = ldu32(&sQh[ar*ALDS + kb]);
            uint32_t a1 = ldu32(&sQh[(ar+8)*ALDS + kb]);
            uint32_t a2 = ldu32(&sQh[ar*ALDS + kb + 8]);
            uint32_t a3 = ldu32(&sQh[(ar+8)*ALDS + kb + 8]);
            uint32_t c0 = ldu32(&sQl[ar*ALDS + kb]);
            uint32_t c1 = ldu32(&sQl[(ar+8)*ALDS + kb]);
            uint32_t c2 = ldu32(&sQl[ar*ALDS + kb + 8]);
            uint32_t c3 = ldu32(&sQl[(ar+8)*ALDS + kb + 8]);
            #pragma unroll
            for (int nt = 0; nt < 8; nt++) {
                const int br = nt*8 + qr;
                uint32_t b0 = ldu32(&sKh[br*ALDS + kb]);
                uint32_t b1 = ldu32(&sKh[br*ALDS + kb + 8]);
                uint32_t d0 = ldu32(&sKl[br*ALDS + kb]);
                uint32_t d1 = ldu32(&sKl[br*ALDS + kb + 8]);
                MMA_BF16(S[nt], a0,a1,a2,a3, b0,b1);
                MMA_BF16(S[nt], c0,c1,c2,c3, b0,b1);
                MMA_BF16(S[nt], a0,a1,a2,a3, d0,d1);
            }
        }

        if (kt >= 2*qt) {   // causal mask on diagonal tiles
            const int ia = qt*128 + r0 + qr;
            #pragma unroll
            for (int nt = 0; nt < 8; nt++) {
                const int j0g = kt*64 + nt*8 + qc*2;
                if (j0g   > ia)   S[nt][0] = -1e30f;
                if (j0g+1 > ia)   S[nt][1] = -1e30f;
                if (j0g   > ia+8) S[nt][2] = -1e30f;
                if (j0g+1 > ia+8) S[nt][3] = -1e30f;
            }
        }

        // online softmax (rows qr, qr+8)
        float mxa = -1e30f, mxb = -1e30f;
        #pragma unroll
        for (int nt = 0; nt < 8; nt++) {
            mxa = fmaxf(mxa, fmaxf(S[nt][0], S[nt][1]));
            mxb = fmaxf(mxb, fmaxf(S[nt][2], S[nt][3]));
        }
        mxa = fmaxf(mxa, __shfl_xor_sync(0xffffffffu, mxa, 1));
        mxa = fmaxf(mxa, __shfl_xor_sync(0xffffffffu, mxa, 2));
        mxb = fmaxf(mxb, __shfl_xor_sync(0xffffffffu, mxb, 1));
        mxb = fmaxf(mxb, __shfl_xor_sync(0xffffffffu, mxb, 2));
        const float mna = fmaxf(m_a, mxa), mnb = fmaxf(m_b, mxb);
        const float ala = __expf(m_a - mna), alb = __expf(m_b - mnb);
        float rsa = 0.0f, rsb = 0.0f;
        #pragma unroll
        for (int nt = 0; nt < 8; nt++) {
            S[nt][0] = __expf(S[nt][0] - mna);
            S[nt][1] = __expf(S[nt][1] - mna);
            S[nt][2] = __expf(S[nt][2] - mnb);
            S[nt][3] = __expf(S[nt][3] - mnb);
            rsa += S[nt][0] + S[nt][1];
            rsb += S[nt][2] + S[nt][3];
        }
        rsa += __shfl_xor_sync(0xffffffffu, rsa, 1);
        rsa += __shfl_xor_sync(0xffffffffu, rsa, 2);
        rsb += __shfl_xor_sync(0xffffffffu, rsb, 1);
        rsb += __shfl_xor_sync(0xffffffffu, rsb, 2);
        l_a = l_a * ala + rsa;  m_a = mna;
        l_b = l_b * alb + rsb;  m_b = mnb;
        #pragma unroll
        for (int nt = 0; nt < 8; nt++) {
            O[nt][0] *= ala; O[nt][1] *= ala;
            O[nt][2] *= alb; O[nt][3] *= alb;
        }

        // P (warp-private rows), split hi/lo
        #pragma unroll
        for (int nt = 0; nt < 8; nt++) {
            uint32_t h, l;
            split_pack(S[nt][0], S[nt][1], h, l);
            *(uint32_t*)&sPh[(r0+qr)*ALDS + nt*8 + qc*2]   = h;
            *(uint32_t*)&sPl[(r0+qr)*ALDS + nt*8 + qc*2]   = l;
            split_pack(S[nt][2], S[nt][3], h, l);
            *(uint32_t*)&sPh[(r0+qr+8)*ALDS + nt*8 + qc*2] = h;
            *(uint32_t*)&sPl[(r0+qr+8)*ALDS + nt*8 + qc*2] = l;
        }
        __syncwarp();

        // O += P V
        #pragma unroll
        for (int ks = 0; ks < 4; ks++) {
            const int kb = ks*16 + qc*2;
            const int ar = r0 + qr;
            uint32_t a0 = ldu32(&sPh[ar*ALDS + kb]);
            uint32_t a1 = ldu32(&sPh[(ar+8)*ALDS + kb]);
            uint32_t a2 = ldu32(&sPh[ar*ALDS + kb + 8]);
            uint32_t a3 = ldu32(&sPh[(ar+8)*ALDS + kb + 8]);
            uint32_t c0 = ldu32(&sPl[ar*ALDS + kb]);
            uint32_t c1 = ldu32(&sPl[(ar+8)*ALDS + kb]);
            uint32_t c2 = ldu32(&sPl[ar*ALDS + kb + 8]);
            uint32_t c3 = ldu32(&sPl[(ar+8)*ALDS + kb + 8]);
            #pragma unroll
            for (int nt = 0; nt < 8; nt++) {
                const int br = nt*8 + qr;
                uint32_t b0 = ldu32(&sVh[br*ALDS + kb]);
                uint32_t b1 = ldu32(&sVh[br*ALDS + kb + 8]);
                uint32_t d0 = ldu32(&sVl[br*ALDS + kb]);
                uint32_t d1 = ldu32(&sVl[br*ALDS + kb + 8]);
                MMA_BF16(O[nt], a0,a1,a2,a3, b0,b1);
                MMA_BF16(O[nt], c0,c1,c2,c3, b0,b1);
                MMA_BF16(O[nt], a0,a1,a2,a3, d0,d1);
            }
        }
    }

    // epilogue: normalize, split, write hi/lo planes in [B,T,H*HS] layout
    const int b = bh / NH, h = bh % NH;
    const float inva = 1.0f / l_a, invb = 1.0f / l_b;
    const int ta = qt*128 + r0 + qr;
    #pragma unroll
    for (int nt = 0; nt < 8; nt++) {
        const int d = nt*8 + qc*2;
        const size_t ia = ((size_t)b*NT + ta)*NC + h*DH + d;
        const size_t ib = ((size_t)b*NT + ta + 8)*NC + h*DH + d;
        uint32_t hh, ll;
        split_pack(O[nt][0]*inva, O[nt][1]*inva, hh, ll);
        *(uint32_t*)&g_ah[ia] = hh;  *(uint32_t*)&g_al[ia] = ll;
        split_pack(O[nt][2]*invb, O[nt][3]*invb, hh, ll);
        *(uint32_t*)&g_ah[ib] = hh;  *(uint32_t*)&g_al[ib] = ll;
    }
}

// ---------------------------------------------------------------------------

extern "C" void kernel_launch(void* const* d_in, const int* in_sizes, int n_in,
                              void* d_out, int out_size)
{
    const float* x  = (const float*)d_in[0];
    const float* Wq = (const float*)d_in[1];
    const float* Wk = (const float*)d_in[2];
    const float* Wv = (const float*)d_in[3];
    const float* Wo = (const float*)d_in[4];
    const float* bo = (const float*)d_in[5];
    float* out = (float*)d_out;

    cudaFuncSetAttribute(gemm_bf16,
                         cudaFuncAttributeMaxDynamicSharedMemorySize, GEMM_SMEM);
    cudaFuncSetAttribute(attn_mma_kernel,
                         cudaFuncAttributeMaxDynamicSharedMemorySize, ATT_SMEM);

    const int n4 = (int)(N4X + 4*N4W);
    convert_kernel<<< n4/256, 256 >>>(x, Wq, Wk, Wv, Wo);
    gemm_bf16<<< dim3(NC/BN, NM/BM, 3), 256, GEMM_SMEM >>>(nullptr, nullptr, 0);
    attn_mma_kernel<<< dim3(NT/128, NB*NH), 256, ATT_SMEM >>>();
    gemm_bf16<<< dim3(NC/BN, NM/BM, 1), 256, GEMM_SMEM >>>(bo, out, 1);
}

// round 9
// speedup vs baseline: 2.9877x; 1.1207x over previous
#include <cuda_runtime.h>
#include <cuda_bf16.h>
#include <cstdint>

// Fixed problem shapes
#define NB 4
#define NT 2048
#define NC 1024
#define NH 16
#define DH 64
#define NM (NB*NT)   // 8192 rows

typedef unsigned short ush;

// Scratch (allocation-free rule: __device__ globals)
__device__ ush g_xh[(size_t)NM*NC], g_xl[(size_t)NM*NC];
__device__ ush g_wh[(size_t)4*NC*NC], g_wl[(size_t)4*NC*NC];
__device__ ush g_qh[(size_t)NB*NH*NT*DH], g_ql[(size_t)NB*NH*NT*DH];
__device__ ush g_kh[(size_t)NB*NH*NT*DH], g_kl[(size_t)NB*NH*NT*DH];
__device__ ush g_vh[(size_t)NB*NH*NT*DH], g_vl[(size_t)NB*NH*NT*DH];
__device__ ush g_ah[(size_t)NM*NC], g_al[(size_t)NM*NC];

__device__ __forceinline__ void split_pack(float x, float y,
                                           uint32_t &hi, uint32_t &lo) {
    __nv_bfloat16 hx = __float2bfloat16_rn(x), hy = __float2bfloat16_rn(y);
    float fx = __bfloat162float(hx), fy = __bfloat162float(hy);
    __nv_bfloat16 lx = __float2bfloat16_rn(x - fx), ly = __float2bfloat16_rn(y - fy);
    hi = ((uint32_t)__bfloat16_as_ushort(hy) << 16) | __bfloat16_as_ushort(hx);
    lo = ((uint32_t)__bfloat16_as_ushort(ly) << 16) | __bfloat16_as_ushort(lx);
}

#define MMA_BF16(d, a0,a1,a2,a3, b0,b1) \
    asm volatile("mma.sync.aligned.m16n8k16.row.col.f32.bf16.bf16.f32 " \
        "{%0,%1,%2,%3}, {%4,%5,%6,%7}, {%8,%9}, {%0,%1,%2,%3};" \
        : "+f"(d[0]), "+f"(d[1]), "+f"(d[2]), "+f"(d[3]) \
        : "r"(a0), "r"(a1), "r"(a2), "r"(a3), "r"(b0), "r"(b1))

#define LDSM4(R0,R1,R2,R3,ADDR) \
    asm volatile("ldmatrix.sync.aligned.m8n8.x4.shared.b16 {%0,%1,%2,%3}, [%4];" \
        : "=r"(R0), "=r"(R1), "=r"(R2), "=r"(R3) : "r"(ADDR))
#define LDSM4T(R0,R1,R2,R3,ADDR) \
    asm volatile("ldmatrix.sync.aligned.m8n8.x4.trans.shared.b16 {%0,%1,%2,%3}, [%4];" \
        : "=r"(R0), "=r"(R1), "=r"(R2), "=r"(R3) : "r"(ADDR))

#define CP16(saddr, gptr) \
    asm volatile("cp.async.cg.shared.global [%0], [%1], 16;" \
                 :: "r"(saddr), "l"(gptr) : "memory")
#define CP_COMMIT() asm volatile("cp.async.commit_group;" ::: "memory")
#define CP_WAIT1()  asm volatile("cp.async.wait_group 1;" ::: "memory")
#define CP_WAIT0()  asm volatile("cp.async.wait_group 0;" ::: "memory")

// ===========================================================================
// One-shot fp32 -> bf16 hi/lo conversion (Wq pre-scaled by sqrt(HS)=8).
// ===========================================================================
#define N4X ((size_t)NM*NC/4)
#define N4W ((size_t)NC*NC/4)

__global__ __launch_bounds__(256) void convert_kernel(
    const float* __restrict__ x,  const float* __restrict__ Wq,
    const float* __restrict__ Wk, const float* __restrict__ Wv,
    const float* __restrict__ Wo)
{
    const size_t i = (size_t)blockIdx.x * blockDim.x + threadIdx.x;
    const float* src;
    ush *dh, *dl;
    float sc = 1.0f;
    if (i < N4X) {
        src = x + i*4; dh = g_xh + i*4; dl = g_xl + i*4;
    } else {
        size_t j = i - N4X;
        size_t w = j / N4W, r = j % N4W;
        const float* ws[4] = {Wq, Wk, Wv, Wo};
        src = ws[w] + r*4;
        dh = g_wh + w*(size_t)NC*NC + r*4;
        dl = g_wl + w*(size_t)NC*NC + r*4;
        if (w == 0) sc = 8.0f;
    }
    float4 v = *(const float4*)src;
    uint32_t h0, l0, h1, l1;
    split_pack(v.x*sc, v.y*sc, h0, l0);
    split_pack(v.z*sc, v.w*sc, h1, l1);
    *(uint32_t*)(dh)   = h0;  *(uint32_t*)(dh+2) = h1;
    *(uint32_t*)(dl)   = l0;  *(uint32_t*)(dl+2) = l1;
}

// ===========================================================================
// 3xBF16 tensor GEMM, cp.async double buffer + ldmatrix fragment loads.
// ===========================================================================
#define BM 128
#define BN 128
#define BK2 32
#define NCHUNK (NC/BK2)
#define SST 40
#define PL (128*SST)
#define PLB (PL*2)             // plane bytes
#define GEMM_SMEM (2*4*PLB)    // 81920

__global__ __launch_bounds__(256) void gemm_bf16(
    const float* __restrict__ bias,
    float* __restrict__ Cout,
    int mode)
{
    extern __shared__ ush sm[];

    const int tid  = threadIdx.x;
    const int wid  = tid >> 5;
    const int lane = tid & 31;
    const int warp_m = wid >> 2;
    const int warp_n = wid & 3;
    const int qr = lane >> 2;
    const int qc = lane & 3;

    const int row0 = blockIdx.y * BM;
    const int col0 = blockIdx.x * BN;

    const ush *Ah, *Al, *Wh, *Wl;
    ush *outh = 0, *outl = 0;
    if (mode == 0) {
        Ah = g_xh; Al = g_xl;
        const size_t wo = (size_t)blockIdx.z * NC * NC;
        Wh = g_wh + wo; Wl = g_wl + wo;
        if (blockIdx.z == 0)      { outh = g_qh; outl = g_ql; }
        else if (blockIdx.z == 1) { outh = g_kh; outl = g_kl; }
        else                      { outh = g_vh; outl = g_vl; }
    } else {
        Ah = g_ah; Al = g_al;
        Wh = g_wh + (size_t)3*NC*NC; Wl = g_wl + (size_t)3*NC*NC;
    }

    const int r  = tid >> 1;
    const int hf = (tid & 1) * 16;
    const ush* gAh = Ah + (size_t)(row0 + r)*NC + hf;
    const ush* gAl = Al + (size_t)(row0 + r)*NC + hf;
    const ush* gBh = Wh + (size_t)(col0 + r)*NC + hf;
    const ush* gBl = Wl + (size_t)(col0 + r)*NC + hf;
    const uint32_t sbase = (uint32_t)__cvta_generic_to_shared(sm);
    const uint32_t soff = (uint32_t)(r*SST + hf) * 2;

    auto load_stage = [&](int c, int s) {
        const uint32_t st = sbase + (uint32_t)s*4*PLB + soff;
        const int g = c * BK2;
        CP16(st,          gAh + g);  CP16(st + 16,        gAh + g + 8);
        CP16(st + PLB,    gAl + g);  CP16(st + PLB+16,    gAl + g + 8);
        CP16(st + 2*PLB,  gBh + g);  CP16(st + 2*PLB+16,  gBh + g + 8);
        CP16(st + 3*PLB,  gBl + g);  CP16(st + 3*PLB+16,  gBl + g + 8);
        CP_COMMIT();
    };

    // ldmatrix per-lane offsets (bytes within a plane)
    const uint32_t a_off = (uint32_t)(((warp_m*64 + (lane&15))*SST + ((lane>>4)<<3)) * 2);
    const uint32_t b_off = (uint32_t)(((warp_n*32 + ((lane&16)>>1) + (lane&7))*SST + (lane&8)) * 2);

    float acc[4][4][4] = {};

    load_stage(0, 0);
    load_stage(1, 1);

    for (int c = 0; c < NCHUNK; c++) {
        if (c == NCHUNK-1) { CP_WAIT0(); } else { CP_WAIT1(); }
        __syncthreads();

        const uint32_t sb = sbase + (uint32_t)(c&1)*4*PLB;

        #pragma unroll
        for (int kk = 0; kk < 2; kk++) {
            const uint32_t ko = (uint32_t)kk * 32;
            uint32_t A0[4][4], A1[4][4], B0[2][4], B1[2][4];
            #pragma unroll
            for (int mi = 0; mi < 4; mi++) {
                const uint32_t ao = sb + a_off + (uint32_t)mi*(16*SST*2) + ko;
                LDSM4(A0[mi][0],A0[mi][1],A0[mi][2],A0[mi][3], ao);
                LDSM4(A1[mi][0],A1[mi][1],A1[mi][2],A1[mi][3], ao + PLB);
            }
            #pragma unroll
            for (int np = 0; np < 2; np++) {
                const uint32_t bo = sb + 2*PLB + b_off + (uint32_t)np*(16*SST*2) + ko;
                LDSM4(B0[np][0],B0[np][1],B0[np][2],B0[np][3], bo);
                LDSM4(B1[np][0],B1[np][1],B1[np][2],B1[np][3], bo + PLB);
            }
            #pragma unroll
            for (int mi = 0; mi < 4; mi++)
                #pragma unroll
                for (int ni = 0; ni < 4; ni++) {
                    const int np = ni >> 1, j = (ni & 1) * 2;
                    MMA_BF16(acc[mi][ni], A0[mi][0],A0[mi][1],A0[mi][2],A0[mi][3], B0[np][j],B0[np][j+1]);
                    MMA_BF16(acc[mi][ni], A1[mi][0],A1[mi][1],A1[mi][2],A1[mi][3], B0[np][j],B0[np][j+1]);
                    MMA_BF16(acc[mi][ni], A0[mi][0],A0[mi][1],A0[mi][2],A0[mi][3], B1[np][j],B1[np][j+1]);
                }
        }
        __syncthreads();
        if (c + 2 < NCHUNK) load_stage(c + 2, c & 1);
    }

    #pragma unroll
    for (int mi = 0; mi < 4; mi++) {
        const int m0 = row0 + warp_m*64 + mi*16 + qr;
        #pragma unroll
        for (int ni = 0; ni < 4; ni++) {
            const int n = col0 + warp_n*32 + ni*8 + qc*2;
            if (mode == 0) {
                const int h = n >> 6, d = n & 63;
                #pragma unroll
                for (int half = 0; half < 2; half++) {
                    const int m = m0 + half*8;
                    const int b = m >> 11, t = m & (NT-1);
                    const size_t idx = (((size_t)b*NH + h)*NT + t)*DH + d;
                    uint32_t hh, ll;
                    split_pack(acc[mi][ni][half*2], acc[mi][ni][half*2+1], hh, ll);
                    *(uint32_t*)&outh[idx] = hh;
                    *(uint32_t*)&outl[idx] = ll;
                }
            } else {
                const float2 bv = *(const float2*)(bias + n);
                #pragma unroll
                for (int half = 0; half < 2; half++) {
                    const int m = m0 + half*8;
                    float* o = Cout + (size_t)m*NC + n;
                    *(float2*)o = make_float2(acc[mi][ni][half*2] + bv.x,
                                              acc[mi][ni][half*2+1] + bv.y);
                }
            }
        }
    }
}

// ===========================================================================
// Tensor-core causal flash attention: Q frags + P in registers, ldmatrix for
// K, ldmatrix.trans for V (stored row-major). 128 q-rows/CTA, Bc=64, 8 warps.
// ===========================================================================
#define ALDS 72
#define AQ_OFF   0
#define AQL_OFF  (128*ALDS)
#define AKH_OFF  (2*128*ALDS)
#define AKL_OFF  (AKH_OFF + 64*ALDS)
#define AVH_OFF  (AKL_OFF + 64*ALDS)
#define AVL_OFF  (AVH_OFF + 64*ALDS)
#define ATT_USH  (AVL_OFF + 64*ALDS)
#define ATT_SMEM (ATT_USH * 2)

__global__ __launch_bounds__(256) void attn_mma_kernel()
{
    extern __shared__ ush su[];

    const int tid  = threadIdx.x;
    const int wid  = tid >> 5;
    const int lane = tid & 31;
    const int qr = lane >> 2;
    const int qc = lane & 3;
    const int r0 = wid * 16;

    const int qt = gridDim.x - 1 - blockIdx.x;
    const int bh = blockIdx.y;

    const uint32_t sbase = (uint32_t)__cvta_generic_to_shared(su);
    const uint32_t qb = sbase + AQ_OFF*2;
    const uint32_t kb = sbase + AKH_OFF*2;
    const uint32_t vb = sbase + AVH_OFF*2;

    // ---- stage Q tile, then hoist fragments to registers ----
    {
        const int lrq = tid >> 1;
        const int lcq = (tid & 1) * 32;
        const size_t qoff = ((size_t)bh*NT + (size_t)qt*128 + lrq)*DH + lcq;
        #pragma unroll
        for (int i = 0; i < 4; i++) {
            *(uint4*)&su[AQ_OFF  + lrq*ALDS + lcq + i*8] = *(const uint4*)(g_qh + qoff + i*8);
            *(uint4*)&su[AQL_OFF + lrq*ALDS + lcq + i*8] = *(const uint4*)(g_ql + qoff + i*8);
        }
    }
    __syncthreads();

    uint32_t Qh[4][4], Ql[4][4];
    {
        const uint32_t a_off = (uint32_t)(((r0 + (lane&15))*ALDS + ((lane>>4)<<3)) * 2);
        #pragma unroll
        for (int ks = 0; ks < 4; ks++) {
            LDSM4(Qh[ks][0],Qh[ks][1],Qh[ks][2],Qh[ks][3], qb + a_off + ks*32);
            LDSM4(Ql[ks][0],Ql[ks][1],Ql[ks][2],Ql[ks][3], qb + (128*ALDS*2) + a_off + ks*32);
        }
    }

    // ldmatrix lane offsets
    const uint32_t kb_off = (uint32_t)(((((lane&16)>>1) + (lane&7))*ALDS + (lane&8)) * 2);
    const uint32_t vb_off = (uint32_t)((((lane&8) + (lane&7))*ALDS + ((lane&16)>>1)) * 2);

    float m_a = -1e30f, m_b = -1e30f, l_a = 0.0f, l_b = 0.0f;
    float O[8][4] = {};

    const int lrk = tid >> 2;
    const int lck = (tid & 3) * 16;

    const int n_kv = 2*qt + 2;
    for (int kt = 0; kt < n_kv; kt++) {
        const size_t koff = ((size_t)bh*NT + (size_t)kt*64 + lrk)*DH + lck;
        uint4 kh0 = *(const uint4*)(g_kh + koff);
        uint4 kh1 = *(const uint4*)(g_kh + koff + 8);
        uint4 kl0 = *(const uint4*)(g_kl + koff);
        uint4 kl1 = *(const uint4*)(g_kl + koff + 8);
        uint4 vh0 = *(const uint4*)(g_vh + koff);
        uint4 vh1 = *(const uint4*)(g_vh + koff + 8);
        uint4 vl0 = *(const uint4*)(g_vl + koff);
        uint4 vl1 = *(const uint4*)(g_vl + koff + 8);
        __syncthreads();

        *(uint4*)&su[AKH_OFF + lrk*ALDS + lck]     = kh0;
        *(uint4*)&su[AKH_OFF + lrk*ALDS + lck + 8] = kh1;
        *(uint4*)&su[AKL_OFF + lrk*ALDS + lck]     = kl0;
        *(uint4*)&su[AKL_OFF + lrk*ALDS + lck + 8] = kl1;
        *(uint4*)&su[AVH_OFF + lrk*ALDS + lck]     = vh0;
        *(uint4*)&su[AVH_OFF + lrk*ALDS + lck + 8] = vh1;
        *(uint4*)&su[AVL_OFF + lrk*ALDS + lck]     = vl0;
        *(uint4*)&su[AVL_OFF + lrk*ALDS + lck + 8] = vl1;
        __syncthreads();

        // ---- S = Q K^T ----
        float S[8][4] = {};
        #pragma unroll
        for (int ks = 0; ks < 4; ks++) {
            #pragma unroll
            for (int np = 0; np < 4; np++) {
                uint32_t B0[4], B1[4];
                const uint32_t bo = kb + kb_off + (uint32_t)np*(16*ALDS*2) + ks*32;
                LDSM4(B0[0],B0[1],B0[2],B0[3], bo);
                LDSM4(B1[0],B1[1],B1[2],B1[3], bo + (64*ALDS*2));
                #pragma unroll
                for (int j = 0; j < 2; j++) {
                    float* s = S[np*2 + j];
                    MMA_BF16(s, Qh[ks][0],Qh[ks][1],Qh[ks][2],Qh[ks][3], B0[j*2],B0[j*2+1]);
                    MMA_BF16(s, Ql[ks][0],Ql[ks][1],Ql[ks][2],Ql[ks][3], B0[j*2],B0[j*2+1]);
                    MMA_BF16(s, Qh[ks][0],Qh[ks][1],Qh[ks][2],Qh[ks][3], B1[j*2],B1[j*2+1]);
                }
            }
        }

        if (kt >= 2*qt) {   // causal mask (diagonal tiles only)
            const int ia = qt*128 + r0 + qr;
            #pragma unroll
            for (int nt = 0; nt < 8; nt++) {
                const int j0g = kt*64 + nt*8 + qc*2;
                if (j0g   > ia)   S[nt][0] = -1e30f;
                if (j0g+1 > ia)   S[nt][1] = -1e30f;
                if (j0g   > ia+8) S[nt][2] = -1e30f;
                if (j0g+1 > ia+8) S[nt][3] = -1e30f;
            }
        }

        // ---- online softmax ----
        float mxa = -1e30f, mxb = -1e30f;
        #pragma unroll
        for (int nt = 0; nt < 8; nt++) {
            mxa = fmaxf(mxa, fmaxf(S[nt][0], S[nt][1]));
            mxb = fmaxf(mxb, fmaxf(S[nt][2], S[nt][3]));
        }
        mxa = fmaxf(mxa, __shfl_xor_sync(0xffffffffu, mxa, 1));
        mxa = fmaxf(mxa, __shfl_xor_sync(0xffffffffu, mxa, 2));
        mxb = fmaxf(mxb, __shfl_xor_sync(0xffffffffu, mxb, 1));
        mxb = fmaxf(mxb, __shfl_xor_sync(0xffffffffu, mxb, 2));
        const float mna = fmaxf(m_a, mxa), mnb = fmaxf(m_b, mxb);
        const float ala = __expf(m_a - mna), alb = __expf(m_b - mnb);
        float rsa = 0.0f, rsb = 0.0f;
        #pragma unroll
        for (int nt = 0; nt < 8; nt++) {
            S[nt][0] = __expf(S[nt][0] - mna);
            S[nt][1] = __expf(S[nt][1] - mna);
            S[nt][2] = __expf(S[nt][2] - mnb);
            S[nt][3] = __expf(S[nt][3] - mnb);
            rsa += S[nt][0] + S[nt][1];
            rsb += S[nt][2] + S[nt][3];
        }
        rsa += __shfl_xor_sync(0xffffffffu, rsa, 1);
        rsa += __shfl_xor_sync(0xffffffffu, rsa, 2);
        rsb += __shfl_xor_sync(0xffffffffu, rsb, 1);
        rsb += __shfl_xor_sync(0xffffffffu, rsb, 2);
        l_a = l_a * ala + rsa;  m_a = mna;
        l_b = l_b * alb + rsb;  m_b = mnb;
        #pragma unroll
        for (int nt = 0; nt < 8; nt++) {
            O[nt][0] *= ala; O[nt][1] *= ala;
            O[nt][2] *= alb; O[nt][3] *= alb;
        }

        // ---- O += P V : P built in registers from S (accumulator->A identity)
        #pragma unroll
        for (int ks = 0; ks < 4; ks++) {
            uint32_t ah[4], al[4];
            split_pack(S[2*ks][0],   S[2*ks][1],   ah[0], al[0]);
            split_pack(S[2*ks][2],   S[2*ks][3],   ah[1], al[1]);
            split_pack(S[2*ks+1][0], S[2*ks+1][1], ah[2], al[2]);
            split_pack(S[2*ks+1][2], S[2*ks+1][3], ah[3], al[3]);
            #pragma unroll
            for (int dp = 0; dp < 4; dp++) {
                uint32_t B0[4], B1[4];
                const uint32_t vo = vb + vb_off + (uint32_t)ks*(16*ALDS*2) + dp*32;
                LDSM4T(B0[0],B0[1],B0[2],B0[3], vo);
                LDSM4T(B1[0],B1[1],B1[2],B1[3], vo + (64*ALDS*2));
                #pragma unroll
                for (int j = 0; j < 2; j++) {
                    float* o = O[dp*2 + j];
                    MMA_BF16(o, ah[0],ah[1],ah[2],ah[3], B0[j*2],B0[j*2+1]);
                    MMA_BF16(o, al[0],al[1],al[2],al[3], B0[j*2],B0[j*2+1]);
                    MMA_BF16(o, ah[0],ah[1],ah[2],ah[3], B1[j*2],B1[j*2+1]);
                }
            }
        }
    }

    // ---- epilogue: normalize, split, write hi/lo planes [B,T,H*HS] ----
    const int b = bh / NH, h = bh % NH;
    const float inva = 1.0f / l_a, invb = 1.0f / l_b;
    const int ta = qt*128 + r0 + qr;
    #pragma unroll
    for (int nt = 0; nt < 8; nt++) {
        const int d = nt*8 + qc*2;
        const size_t ia = ((size_t)b*NT + ta)*NC + h*DH + d;
        const size_t ib = ((size_t)b*NT + ta + 8)*NC + h*DH + d;
        uint32_t hh, ll;
        split_pack(O[nt][0]*inva, O[nt][1]*inva, hh, ll);
        *(uint32_t*)&g_ah[ia] = hh;  *(uint32_t*)&g_al[ia] = ll;
        split_pack(O[nt][2]*invb, O[nt][3]*invb, hh, ll);
        *(uint32_t*)&g_ah[ib] = hh;  *(uint32_t*)&g_al[ib] = ll;
    }
}

// ---------------------------------------------------------------------------

extern "C" void kernel_launch(void* const* d_in, const int* in_sizes, int n_in,
                              void* d_out, int out_size)
{
    const float* x  = (const float*)d_in[0];
    const float* Wq = (const float*)d_in[1];
    const float* Wk = (const float*)d_in[2];
    const float* Wv = (const float*)d_in[3];
    const float* Wo = (const float*)d_in[4];
    const float* bo = (const float*)d_in[5];
    float* out = (float*)d_out;

    cudaFuncSetAttribute(gemm_bf16,
                         cudaFuncAttributeMaxDynamicSharedMemorySize, GEMM_SMEM);
    cudaFuncSetAttribute(attn_mma_kernel,
                         cudaFuncAttributeMaxDynamicSharedMemorySize, ATT_SMEM);

    const int n4 = (int)(N4X + 4*N4W);
    convert_kernel<<< n4/256, 256 >>>(x, Wq, Wk, Wv, Wo);
    gemm_bf16<<< dim3(NC/BN, NM/BM, 3), 256, GEMM_SMEM >>>(nullptr, nullptr, 0);
    attn_mma_kernel<<< dim3(NT/128, NB*NH), 256, ATT_SMEM >>>();
    gemm_bf16<<< dim3(NC/BN, NM/BM, 1), 256, GEMM_SMEM >>>(bo, out, 1);
}